// round 10
// baseline (speedup 1.0000x reference)
#include <cuda_runtime.h>
#include <cuda_fp16.h>
#include <math.h>
#include <stdint.h>

#define Bb 4
#define Ss 8192
#define Ff 512
#define Hh 2048
#define BSr 32768
#define KCB 768
typedef __half fp16;

__device__ __align__(256) float  d_bu[(size_t)BSr*256];
__device__ __align__(256) fp16   d_comb[(size_t)BSr*KCB];   // cols 0..255 xs, 256..767 h
__device__ __align__(256) fp16   d_h2[(size_t)BSr*Ff];
__device__ __align__(256) fp16   d_g[(size_t)BSr*Hh];
__device__ __align__(256) float  d_x1[(size_t)BSr*Ff];
__device__ float  d_mods[Bb*6*Ff];
__device__ float2 d_abar[128];
__device__ float2 d_car[Bb*2*128*64];
__device__ float2 d_off[Bb*2*128*64];
__device__ __align__(256) fp16   d_wbu[256*Ff];
__device__ __align__(256) fp16   d_wc[Ff*KCB];
__device__ __align__(256) fp16   d_w1[(size_t)Hh*Ff];
__device__ __align__(256) fp16   d_w2[(size_t)Ff*Hh];

__device__ __forceinline__ uint32_t s2u(const void* p){
    uint32_t a;
    asm("{ .reg .u64 t; cvta.to.shared.u64 t, %1; cvt.u32.u64 %0, t; }":"=r"(a):"l"(p));
    return a;
}
__device__ __forceinline__ uint32_t sw64(uint32_t o){ return o ^ ((o >> 3) & 0x30u); }
__device__ __forceinline__ void cpa16(uint32_t d, const void* s){
    asm volatile("cp.async.cg.shared.global [%0], [%1], 16;"::"r"(d),"l"(s));
}
#define CPC() asm volatile("cp.async.commit_group;")
#define CPW(n) asm volatile("cp.async.wait_group %0;"::"n"(n))

__device__ __forceinline__ void ldmx4(uint32_t* r, uint32_t a){
    asm volatile("ldmatrix.sync.aligned.m8n8.x4.shared.b16 {%0,%1,%2,%3}, [%4];"
        :"=r"(r[0]),"=r"(r[1]),"=r"(r[2]),"=r"(r[3]):"r"(a));
}
__device__ __forceinline__ void hmma(float* d, const uint32_t* a, const uint32_t* b){
    asm volatile("mma.sync.aligned.m16n8k16.row.col.f32.f16.f16.f32 "
        "{%0,%1,%2,%3}, {%4,%5,%6,%7}, {%8,%9}, {%0,%1,%2,%3};"
        : "+f"(d[0]),"+f"(d[1]),"+f"(d[2]),"+f"(d[3])
        : "r"(a[0]),"r"(a[1]),"r"(a[2]),"r"(a[3]),"r"(b[0]),"r"(b[1]));
}
// gelu(tanh approx) == x * sigmoid(1.59577*(x + 0.044715 x^3))
__device__ __forceinline__ float fast_gelu(float x){
    float u = x*(1.0f + 0.044715f*x*x);
    float e = __expf(-1.5957691216057308f*u);
    return x * __frcp_rn(1.0f + e);
}

// ---------------- prep ----------------
__global__ void prep_mods_k(const float* __restrict__ cond, const float* __restrict__ aw,
                            const float* __restrict__ ab) {
    __shared__ float sc[Ff];
    int b = blockIdx.y;
    for (int i = threadIdx.x; i < Ff; i += 256) {
        float v = cond[b*Ff + i];
        sc[i] = v * __frcp_rn(1.0f + __expf(-v));
    }
    __syncthreads();
    int j = blockIdx.x*256 + threadIdx.x;
    float acc = ab[j];
    #pragma unroll 8
    for (int f = 0; f < Ff; f++) acc += sc[f]*aw[f*(6*Ff)+j];
    d_mods[b*(6*Ff)+j] = acc;
}

__global__ void prep_ssm_k(const float* fla, const float* fai, const float* fbr,
                           const float* fbi, const float* fld,
                           const float* bla, const float* bai, const float* bbr,
                           const float* bbi, const float* bld) {
    int n = blockIdx.x & 63, dir = blockIdx.x >> 6;
    const float* la = dir?bla:fla; const float* ai = dir?bai:fai;
    const float* br = dir?bbr:fbr; const float* bi = dir?bbi:fbi;
    const float* ld = dir?bld:fld;
    float dt = expf(ld[n]), Are = -expf(la[n]), Aim = ai[n];
    float er = expf(Are*dt);
    float abr = er*cosf(Aim*dt), abi = er*sinf(Aim*dt);
    float dre = Are + 1e-8f, dim = Aim;
    float den = dre*dre + dim*dim;
    float nre = abr - 1.0f, nim = abi;
    float cre = (nre*dre + nim*dim)/den, cim = (nim*dre - nre*dim)/den;
    if (threadIdx.x == 0) d_abar[dir*64+n] = make_float2(abr, abi);
    int f = threadIdx.x;
    float bre = br[n*Ff+f], bim = bi[n*Ff+f];
    d_wbu[(dir*128+n)*Ff+f]    = __float2half_rn(cre*bre - cim*bim);
    d_wbu[(dir*128+64+n)*Ff+f] = __float2half_rn(cre*bim + cim*bre);
}

// merged: blocks 0..255 build xs-part of Wc (C^T P), blocks 256..767 build h-part
__global__ void prep_wc_k(const float* fcr, const float* fci, const float* bcr,
                          const float* bci, const float* Df, const float* Db,
                          const float* pw) {
    if (blockIdx.x < 256) {
        int ch = blockIdx.x, blk = ch>>6, n = ch&63;
        const float* C = (blk==0)?fcr:(blk==1)?fci:(blk==2)?bcr:bci;
        float sign = (blk==1||blk==3)?-1.0f:1.0f;
        int poff = (blk>=2)?Ff:0;
        __shared__ float sC[Ff];
        for (int i = threadIdx.x; i < Ff; i += 512) sC[i] = C[i*64+n];
        __syncthreads();
        int fp = threadIdx.x;
        float acc = 0.0f;
        #pragma unroll 8
        for (int f = 0; f < Ff; f++) acc += sC[f]*pw[(poff+f)*Ff+fp];
        d_wc[(size_t)fp*KCB+ch] = __float2half_rn(sign*acc);
    } else {
        int idx = (blockIdx.x - 256)*512 + threadIdx.x;   // 0..262143
        int f = idx>>9, fp = idx&511;
        float v = Df[f]*pw[idx] + Db[f]*pw[idx+Ff*Ff];
        d_wc[(size_t)fp*KCB+256+f] = __float2half_rn(v);
    }
}

// merged transpose for w1 (2048x512 <- 512x2048) and w2 (512x2048 <- 2048x512)
__global__ void transpose_k(const float* __restrict__ s1, fp16* d1,
                            const float* __restrict__ s2, fp16* d2) {
    __shared__ float t[32][33];
    int id = blockIdx.x;
    const float* s; fp16* d; int R, C, bx, by;
    if (id < 1024) { s = s1; d = d1; R = Ff; C = Hh; bx = (id & 63)*32; by = (id >> 6)*32; }
    else { id -= 1024; s = s2; d = d2; R = Hh; C = Ff; bx = (id & 15)*32; by = (id >> 4)*32; }
    int tx = threadIdx.x & 31, ty = threadIdx.x >> 5;
    #pragma unroll
    for (int i = 0; i < 32; i += 8) t[ty+i][tx] = s[(size_t)(by+ty+i)*C + bx+tx];
    __syncthreads();
    #pragma unroll
    for (int i = 0; i < 32; i += 8)
        d[(size_t)(bx+ty+i)*R + by+tx] = __float2half_rn(t[tx][ty+i]);
}

__global__ void ln_mod_k(const float* __restrict__ in, fp16* __restrict__ oh,
                         int ld, int moff) {
    int row = blockIdx.x, bb = row>>13, tid = threadIdx.x;
    float4 v = ((const float4*)(in + (size_t)row*Ff))[tid];
    float s = v.x+v.y+v.z+v.w, sq = v.x*v.x+v.y*v.y+v.z*v.z+v.w*v.w;
    #pragma unroll
    for (int o = 16; o > 0; o >>= 1) {
        s += __shfl_down_sync(~0u, s, o); sq += __shfl_down_sync(~0u, sq, o);
    }
    __shared__ float ss[4], sv[4];
    int w = tid>>5, l = tid&31;
    if (l==0){ ss[w]=s; sv[w]=sq; }
    __syncthreads();
    if (tid==0){ ss[0]+=ss[1]+ss[2]+ss[3]; sv[0]+=sv[1]+sv[2]+sv[3]; }
    __syncthreads();
    float mu = ss[0]*(1.0f/512.0f), var = sv[0]*(1.0f/512.0f) - mu*mu;
    float rs = rsqrtf(var + 1e-5f);
    const float* md = d_mods + bb*(6*Ff) + moff;
    int f = tid*4;
    float o0 = (v.x-mu)*rs*(1.0f+md[Ff+f+0]) + md[f+0];
    float o1 = (v.y-mu)*rs*(1.0f+md[Ff+f+1]) + md[f+1];
    float o2 = (v.z-mu)*rs*(1.0f+md[Ff+f+2]) + md[f+2];
    float o3 = (v.w-mu)*rs*(1.0f+md[Ff+f+3]) + md[f+3];
    fp16 h4[4] = {__float2half_rn(o0), __float2half_rn(o1),
                  __float2half_rn(o2), __float2half_rn(o3)};
    *(uint2*)&oh[(size_t)row*ld + f] = *(uint2*)h4;
}

// ---------------- HMMA GEMM: C[M,N] = A @ B^T  (fp16 in, fp32 accum) ----------
// 128x256 CTA tile, 512 threads = 16 warps of 64x32, K-chunk 64 (two subs),
// double-buffered cp.async. Sub-stage: A 8KB + B 16KB = 24KB; stage 48KB; x2 = 96KB.
#define SUBSZ 24576u
#define STGSZ 49152u
__device__ __forceinline__ void load_sub(uint32_t b,
    const fp16* __restrict__ A, int lda, const fp16* __restrict__ B, int ldb,
    int m0, int n0, int kc, int tid) {
    { // A: 128 rows x 4 chunks = 512 entries
        int row = tid >> 2, c16 = tid & 3;
        uint32_t o = sw64((uint32_t)(row*64 + c16*16));
        cpa16(b + o, A + (size_t)(m0+row)*lda + kc + c16*8);
    }
    #pragma unroll
    for (int i = 0; i < 2; i++) { // B: 256 rows x 4 chunks = 1024 entries
        int j = tid + i*512;
        int row = j >> 2, c16 = j & 3;
        uint32_t o = sw64((uint32_t)(row*64 + c16*16));
        cpa16(b + 8192 + o, B + (size_t)(n0+row)*ldb + kc + c16*8);
    }
}
__device__ __forceinline__ void load_stage(uint32_t b,
    const fp16* __restrict__ A, int lda, const fp16* __restrict__ B, int ldb,
    int m0, int n0, int kc, int tid) {
    load_sub(b,         A, lda, B, ldb, m0, n0, kc,      tid);
    load_sub(b + SUBSZ, A, lda, B, ldb, m0, n0, kc + 32, tid);
}

// EPI: 0 fp32 C  1 x1=aux1+g1*(v+aux2)  2 gelu(v+aux2)->fp16  3 aux1+g2*(v+aux2)
template<int EPI>
__global__ __launch_bounds__(512, 1) void gemm_tc(
    const fp16* __restrict__ A, int lda,
    const fp16* __restrict__ B, int ldb, int K,
    float* __restrict__ C, int ldc, const float* __restrict__ aux1,
    const float* __restrict__ aux2, fp16* __restrict__ obh)
{
    extern __shared__ char dsm[];
    uint32_t sb = (s2u(dsm) + 1023u) & ~1023u;
    int tid = threadIdx.x;
    int n0 = blockIdx.x*256, m0 = blockIdx.y*128;
    int wid = tid>>5, lane = tid&31;
    int wm = wid>>3, wn = wid&7;     // warp tile: rows wm*64, cols wn*32

    float acc[4][4][4];
    #pragma unroll
    for (int a = 0; a < 4; a++)
        #pragma unroll
        for (int bq = 0; bq < 4; bq++)
            #pragma unroll
            for (int r = 0; r < 4; r++) acc[a][bq][r] = 0.0f;

    const int NC = K >> 6;
    load_stage(sb, A, lda, B, ldb, m0, n0, 0, tid);
    CPC();
    for (int c = 0; c < NC; c++) {
        uint32_t cur = sb + (uint32_t)(c & 1)*STGSZ;
        if (c + 1 < NC) {
            load_stage(sb + (uint32_t)((c+1)&1)*STGSZ, A, lda, B, ldb,
                       m0, n0, (c+1)<<6, tid);
            CPC();
            CPW(1);
        } else {
            CPW(0);
        }
        __syncthreads();
        #pragma unroll
        for (int ks4 = 0; ks4 < 4; ks4++) {
            uint32_t sub = cur + (uint32_t)(ks4 >> 1)*SUBSZ;
            int ks = ks4 & 1;
            uint32_t af[4][4], bf[4][2];
            #pragma unroll
            for (int mt = 0; mt < 4; mt++) {
                int row = wm*64 + mt*16 + (lane & 15);
                int ch  = ks*2 + (lane >> 4);
                ldmx4(af[mt], sub + sw64((uint32_t)(row*64 + ch*16)));
            }
            #pragma unroll
            for (int bp = 0; bp < 2; bp++) {
                int mi = lane >> 3;
                int row = wn*32 + bp*16 + (mi >> 1)*8 + (lane & 7);
                int ch  = ks*2 + (mi & 1);
                uint32_t r[4];
                ldmx4(r, sub + 8192 + sw64((uint32_t)(row*64 + ch*16)));
                bf[bp*2][0]=r[0]; bf[bp*2][1]=r[1]; bf[bp*2+1][0]=r[2]; bf[bp*2+1][1]=r[3];
            }
            #pragma unroll
            for (int mt = 0; mt < 4; mt++)
                #pragma unroll
                for (int nt = 0; nt < 4; nt++)
                    hmma(acc[mt][nt], af[mt], bf[nt]);
        }
        __syncthreads();
    }

    int g = lane >> 2, tig = lane & 3;
    #pragma unroll
    for (int mt = 0; mt < 4; mt++) {
        #pragma unroll
        for (int nt = 0; nt < 4; nt++) {
            int n = n0 + wn*32 + nt*8 + tig*2;
            #pragma unroll
            for (int half = 0; half < 2; half++) {
                int m = m0 + wm*64 + mt*16 + g + half*8;
                float v0 = acc[mt][nt][half*2+0], v1 = acc[mt][nt][half*2+1];
                if (EPI == 0) {
                    float2 o = {v0, v1};
                    *(float2*)&C[(size_t)m*ldc + n] = o;
                } else if (EPI == 1 || EPI == 3) {
                    int bb = m >> 13;
                    const float* md = d_mods + bb*(6*Ff) + (EPI==1 ? 2*Ff : 5*Ff);
                    float2 o;
                    o.x = aux1[(size_t)m*Ff + n+0] + md[n+0]*(v0 + aux2[n+0]);
                    o.y = aux1[(size_t)m*Ff + n+1] + md[n+1]*(v1 + aux2[n+1]);
                    *(float2*)&C[(size_t)m*ldc + n] = o;
                } else {
                    fp16 hp[2];
                    hp[0] = __float2half_rn(fast_gelu(v0 + aux2[n+0]));
                    hp[1] = __float2half_rn(fast_gelu(v1 + aux2[n+1]));
                    *(uint32_t*)&obh[(size_t)m*ldc + n] = *(uint32_t*)hp;
                }
            }
        }
    }
}

// ---------------- 3-phase scan over row-major Bu[32768][256] -----------------
__global__ __launch_bounds__(64) void scan_local_k() {
    int c = threadIdx.x, chunk = blockIdx.x, b = blockIdx.y, dir = blockIdx.z;
    int rc = dir ? 128+c : c, ic = rc+64;
    float2 a = d_abar[dir*64+c];
    float* p = d_bu + (size_t)(b*Ss + chunk*64)*256;
    float re[64], im[64];
    #pragma unroll
    for (int j = 0; j < 64; j++) {
        int s = dir ? 63-j : j;
        re[j] = p[s*256+rc]; im[j] = p[s*256+ic];
    }
    float xr = 0.0f, xi = 0.0f;
    #pragma unroll
    for (int j = 0; j < 64; j++) {
        float nr = a.x*xr - a.y*xi + re[j];
        float ni = a.x*xi + a.y*xr + im[j];
        xr = nr; xi = ni; re[j] = xr; im[j] = xi;
    }
    #pragma unroll
    for (int j = 0; j < 64; j++) {
        int s = dir ? 63-j : j;
        p[s*256+rc] = re[j]; p[s*256+ic] = im[j];
    }
    d_car[(((size_t)(b*2+dir))*128 + chunk)*64 + c] = make_float2(xr, xi);
}

__global__ void scan_combine_k() {
    int tid = threadIdx.x;
    int b = tid>>7, dir = (tid>>6)&1, c = tid&63;
    float2 a = d_abar[dir*64+c], a64 = a;
    #pragma unroll
    for (int i = 0; i < 6; i++) {
        float t = a64.x*a64.x - a64.y*a64.y;
        a64.y = 2.0f*a64.x*a64.y; a64.x = t;
    }
    size_t base = ((size_t)(b*2+dir))*128*64 + c;
    float ox = 0.0f, oy = 0.0f;
    for (int k = 0; k < 128; k++) {
        int ch = dir ? 127-k : k;
        float2 cr = d_car[base + (size_t)ch*64];
        d_off[base + (size_t)ch*64] = make_float2(ox, oy);
        float nx = a64.x*ox - a64.y*oy + cr.x;
        float ny = a64.x*oy + a64.y*ox + cr.y;
        ox = nx; oy = ny;
    }
}

__global__ __launch_bounds__(64) void scan_apply_k() {
    int c = threadIdx.x, chunk = blockIdx.x, b = blockIdx.y, dir = blockIdx.z;
    int rc = dir ? 128+c : c, ic = rc+64;
    float2 a = d_abar[dir*64+c];
    float2 O = d_off[(((size_t)(b*2+dir))*128 + chunk)*64 + c];
    const float* p = d_bu + (size_t)(b*Ss + chunk*64)*256;
    size_t rb = (size_t)(b*Ss + chunk*64);
    float px = a.x, py = a.y;
    #pragma unroll
    for (int j = 0; j < 64; j++) {
        int s = dir ? 63-j : j;
        float vr = p[s*256+rc] + (px*O.x - py*O.y);
        float vi = p[s*256+ic] + (px*O.y + py*O.x);
        float np = px*a.x - py*a.y;
        py = px*a.y + py*a.x; px = np;
        size_t ro = (rb + s)*KCB;
        d_comb[ro+rc] = __float2half_rn(vr);
        d_comb[ro+ic] = __float2half_rn(vi);
    }
}

// ---------------- launcher ----------------------------------------------------
extern "C" void kernel_launch(void* const* d_in, const int* in_sizes, int n_in,
                              void* d_out, int out_size) {
    const float* x      = (const float*)d_in[0];
    const float* cond   = (const float*)d_in[1];
    const float* f_la   = (const float*)d_in[2];
    const float* f_ai   = (const float*)d_in[3];
    const float* f_br   = (const float*)d_in[4];
    const float* f_bi   = (const float*)d_in[5];
    const float* f_cr   = (const float*)d_in[6];
    const float* f_ci   = (const float*)d_in[7];
    const float* f_d    = (const float*)d_in[8];
    const float* f_ld   = (const float*)d_in[9];
    const float* b_la   = (const float*)d_in[10];
    const float* b_ai   = (const float*)d_in[11];
    const float* b_br   = (const float*)d_in[12];
    const float* b_bi   = (const float*)d_in[13];
    const float* b_cr   = (const float*)d_in[14];
    const float* b_ci   = (const float*)d_in[15];
    const float* b_d    = (const float*)d_in[16];
    const float* b_ld   = (const float*)d_in[17];
    const float* proj_w = (const float*)d_in[18];
    const float* proj_b = (const float*)d_in[19];
    const float* ada_w  = (const float*)d_in[20];
    const float* ada_b  = (const float*)d_in[21];
    const float* mlp_w1 = (const float*)d_in[22];
    const float* mlp_b1 = (const float*)d_in[23];
    const float* mlp_w2 = (const float*)d_in[24];
    const float* mlp_b2 = (const float*)d_in[25];
    float* out = (float*)d_out;

    const int DSM = 2*49152 + 1024;
    cudaFuncSetAttribute(gemm_tc<0>, cudaFuncAttributeMaxDynamicSharedMemorySize, DSM);
    cudaFuncSetAttribute(gemm_tc<1>, cudaFuncAttributeMaxDynamicSharedMemorySize, DSM);
    cudaFuncSetAttribute(gemm_tc<2>, cudaFuncAttributeMaxDynamicSharedMemorySize, DSM);
    cudaFuncSetAttribute(gemm_tc<3>, cudaFuncAttributeMaxDynamicSharedMemorySize, DSM);

    float *bu, *x1; fp16 *comb, *h2, *g, *wbu, *wc, *w1, *w2;
    cudaGetSymbolAddress((void**)&bu, d_bu);
    cudaGetSymbolAddress((void**)&x1, d_x1);
    cudaGetSymbolAddress((void**)&comb, d_comb);
    cudaGetSymbolAddress((void**)&h2, d_h2);
    cudaGetSymbolAddress((void**)&g, d_g);
    cudaGetSymbolAddress((void**)&wbu, d_wbu);
    cudaGetSymbolAddress((void**)&wc, d_wc);
    cudaGetSymbolAddress((void**)&w1, d_w1);
    cudaGetSymbolAddress((void**)&w2, d_w2);

    prep_mods_k<<<dim3(12,4), 256>>>(cond, ada_w, ada_b);
    prep_ssm_k<<<128, 512>>>(f_la,f_ai,f_br,f_bi,f_ld, b_la,b_ai,b_br,b_bi,b_ld);
    prep_wc_k<<<768, 512>>>(f_cr, f_ci, b_cr, b_ci, f_d, b_d, proj_w);
    transpose_k<<<2048, 256>>>(mlp_w1, w1, mlp_w2, w2);
    ln_mod_k<<<BSr, 128>>>(x, comb+256, KCB, 0);

    // Bu[32768,256] = h @ Wbu^T
    gemm_tc<0><<<dim3(1,256), 512, DSM>>>(comb+256, KCB, wbu, Ff, Ff,
                                          bu, 256, nullptr, nullptr, nullptr);
    scan_local_k<<<dim3(128,4,2), 64>>>();
    scan_combine_k<<<1, 512>>>();
    scan_apply_k<<<dim3(128,4,2), 64>>>();

    // x1 = x + g1*(comb @ Wc^T + proj_b)
    gemm_tc<1><<<dim3(2,256), 512, DSM>>>(comb, KCB, wc, KCB, KCB,
                                          x1, Ff, x, proj_b, nullptr);

    // h2 = modulated LN(x1)
    ln_mod_k<<<BSr, 128>>>(x1, h2, Ff, 3*Ff);

    // g = gelu(h2 @ W1^T + b1) -> fp16
    gemm_tc<2><<<dim3(8,256), 512, DSM>>>(h2, Ff, w1, Ff, Ff,
                                          nullptr, Hh, nullptr, mlp_b1, g);

    // out = x1 + g2*(g @ W2^T + b2)
    gemm_tc<3><<<dim3(2,256), 512, DSM>>>(g, Hh, w2, Hh, Hh,
                                          out, Ff, x1, mlp_b2, nullptr);
}

// round 11
// speedup vs baseline: 1.1659x; 1.1659x over previous
#include <cuda_runtime.h>
#include <cuda_fp16.h>
#include <math.h>
#include <stdint.h>

#define Bb 4
#define Ss 8192
#define Ff 512
#define Hh 2048
#define BSr 32768
#define KCB 768
typedef __half fp16;

__device__ __align__(256) float  d_bu[(size_t)BSr*256];
__device__ __align__(256) fp16   d_comb[(size_t)BSr*KCB];   // cols 0..255 xs, 256..767 h
__device__ __align__(256) fp16   d_h2[(size_t)BSr*Ff];
__device__ __align__(256) fp16   d_g[(size_t)BSr*Hh];
__device__ __align__(256) float  d_x1[(size_t)BSr*Ff];
__device__ float  d_mods[Bb*6*Ff];
__device__ float2 d_abar[128];
__device__ float2 d_car[Bb*2*128*64];
__device__ float2 d_off[Bb*2*128*64];
__device__ __align__(256) fp16   d_wbu[256*Ff];
__device__ __align__(256) fp16   d_wc[Ff*KCB];
__device__ __align__(256) fp16   d_w1[(size_t)Hh*Ff];
__device__ __align__(256) fp16   d_w2[(size_t)Ff*Hh];

__device__ __forceinline__ uint32_t s2u(const void* p){
    uint32_t a;
    asm("{ .reg .u64 t; cvta.to.shared.u64 t, %1; cvt.u32.u64 %0, t; }":"=r"(a):"l"(p));
    return a;
}
__device__ __forceinline__ uint32_t sw64(uint32_t o){ return o ^ ((o >> 3) & 0x30u); }
__device__ __forceinline__ void cpa16(uint32_t d, const void* s){
    asm volatile("cp.async.cg.shared.global [%0], [%1], 16;"::"r"(d),"l"(s));
}
#define CPC() asm volatile("cp.async.commit_group;")
#define CPW(n) asm volatile("cp.async.wait_group %0;"::"n"(n))

__device__ __forceinline__ void ldmx4(uint32_t* r, uint32_t a){
    asm volatile("ldmatrix.sync.aligned.m8n8.x4.shared.b16 {%0,%1,%2,%3}, [%4];"
        :"=r"(r[0]),"=r"(r[1]),"=r"(r[2]),"=r"(r[3]):"r"(a));
}
__device__ __forceinline__ void hmma(float* d, const uint32_t* a, const uint32_t* b){
    asm volatile("mma.sync.aligned.m16n8k16.row.col.f32.f16.f16.f32 "
        "{%0,%1,%2,%3}, {%4,%5,%6,%7}, {%8,%9}, {%0,%1,%2,%3};"
        : "+f"(d[0]),"+f"(d[1]),"+f"(d[2]),"+f"(d[3])
        : "r"(a[0]),"r"(a[1]),"r"(a[2]),"r"(a[3]),"r"(b[0]),"r"(b[1]));
}
// gelu(tanh approx) == x * sigmoid(1.59577*(x + 0.044715 x^3))
__device__ __forceinline__ float fast_gelu(float x){
    float u = x*(1.0f + 0.044715f*x*x);
    float e = __expf(-1.5957691216057308f*u);
    return x * __frcp_rn(1.0f + e);
}

// ---------------- prep ----------------
__global__ void prep_mods_k(const float* __restrict__ cond, const float* __restrict__ aw,
                            const float* __restrict__ ab) {
    __shared__ float sc[Ff];
    int b = blockIdx.y;
    for (int i = threadIdx.x; i < Ff; i += 256) {
        float v = cond[b*Ff + i];
        sc[i] = v * __frcp_rn(1.0f + __expf(-v));
    }
    __syncthreads();
    int j = blockIdx.x*256 + threadIdx.x;
    float acc = ab[j];
    #pragma unroll 8
    for (int f = 0; f < Ff; f++) acc += sc[f]*aw[f*(6*Ff)+j];
    d_mods[b*(6*Ff)+j] = acc;
}

__global__ void prep_ssm_k(const float* fla, const float* fai, const float* fbr,
                           const float* fbi, const float* fld,
                           const float* bla, const float* bai, const float* bbr,
                           const float* bbi, const float* bld) {
    int n = blockIdx.x & 63, dir = blockIdx.x >> 6;
    const float* la = dir?bla:fla; const float* ai = dir?bai:fai;
    const float* br = dir?bbr:fbr; const float* bi = dir?bbi:fbi;
    const float* ld = dir?bld:fld;
    float dt = expf(ld[n]), Are = -expf(la[n]), Aim = ai[n];
    float er = expf(Are*dt);
    float abr = er*cosf(Aim*dt), abi = er*sinf(Aim*dt);
    float dre = Are + 1e-8f, dim = Aim;
    float den = dre*dre + dim*dim;
    float nre = abr - 1.0f, nim = abi;
    float cre = (nre*dre + nim*dim)/den, cim = (nim*dre - nre*dim)/den;
    if (threadIdx.x == 0) d_abar[dir*64+n] = make_float2(abr, abi);
    int f = threadIdx.x;
    float bre = br[n*Ff+f], bim = bi[n*Ff+f];
    d_wbu[(dir*128+n)*Ff+f]    = __float2half_rn(cre*bre - cim*bim);
    d_wbu[(dir*128+64+n)*Ff+f] = __float2half_rn(cre*bim + cim*bre);
}

// merged: blocks 0..255 build xs-part of Wc (C^T P), blocks 256..767 build h-part
__global__ void prep_wc_k(const float* fcr, const float* fci, const float* bcr,
                          const float* bci, const float* Df, const float* Db,
                          const float* pw) {
    if (blockIdx.x < 256) {
        int ch = blockIdx.x, blk = ch>>6, n = ch&63;
        const float* C = (blk==0)?fcr:(blk==1)?fci:(blk==2)?bcr:bci;
        float sign = (blk==1||blk==3)?-1.0f:1.0f;
        int poff = (blk>=2)?Ff:0;
        __shared__ float sC[Ff];
        for (int i = threadIdx.x; i < Ff; i += 512) sC[i] = C[i*64+n];
        __syncthreads();
        int fp = threadIdx.x;
        float acc = 0.0f;
        #pragma unroll 8
        for (int f = 0; f < Ff; f++) acc += sC[f]*pw[(poff+f)*Ff+fp];
        d_wc[(size_t)fp*KCB+ch] = __float2half_rn(sign*acc);
    } else {
        int idx = (blockIdx.x - 256)*512 + threadIdx.x;   // 0..262143
        int f = idx>>9, fp = idx&511;
        float v = Df[f]*pw[idx] + Db[f]*pw[idx+Ff*Ff];
        d_wc[(size_t)fp*KCB+256+f] = __float2half_rn(v);
    }
}

// merged transpose for w1 (2048x512 <- 512x2048) and w2 (512x2048 <- 2048x512)
__global__ void transpose_k(const float* __restrict__ s1, fp16* d1,
                            const float* __restrict__ s2, fp16* d2) {
    __shared__ float t[32][33];
    int id = blockIdx.x;
    const float* s; fp16* d; int R, C, bx, by;
    if (id < 1024) { s = s1; d = d1; R = Ff; C = Hh; bx = (id & 63)*32; by = (id >> 6)*32; }
    else { id -= 1024; s = s2; d = d2; R = Hh; C = Ff; bx = (id & 15)*32; by = (id >> 4)*32; }
    int tx = threadIdx.x & 31, ty = threadIdx.x >> 5;
    #pragma unroll
    for (int i = 0; i < 32; i += 8) t[ty+i][tx] = s[(size_t)(by+ty+i)*C + bx+tx];
    __syncthreads();
    #pragma unroll
    for (int i = 0; i < 32; i += 8)
        d[(size_t)(bx+ty+i)*R + by+tx] = __float2half_rn(t[tx][ty+i]);
}

__global__ void ln_mod_k(const float* __restrict__ in, fp16* __restrict__ oh,
                         int ld, int moff) {
    int row = blockIdx.x, bb = row>>13, tid = threadIdx.x;
    float4 v = ((const float4*)(in + (size_t)row*Ff))[tid];
    float s = v.x+v.y+v.z+v.w, sq = v.x*v.x+v.y*v.y+v.z*v.z+v.w*v.w;
    #pragma unroll
    for (int o = 16; o > 0; o >>= 1) {
        s += __shfl_down_sync(~0u, s, o); sq += __shfl_down_sync(~0u, sq, o);
    }
    __shared__ float ss[4], sv[4];
    int w = tid>>5, l = tid&31;
    if (l==0){ ss[w]=s; sv[w]=sq; }
    __syncthreads();
    if (tid==0){ ss[0]+=ss[1]+ss[2]+ss[3]; sv[0]+=sv[1]+sv[2]+sv[3]; }
    __syncthreads();
    float mu = ss[0]*(1.0f/512.0f), var = sv[0]*(1.0f/512.0f) - mu*mu;
    float rs = rsqrtf(var + 1e-5f);
    const float* md = d_mods + bb*(6*Ff) + moff;
    int f = tid*4;
    float o0 = (v.x-mu)*rs*(1.0f+md[Ff+f+0]) + md[f+0];
    float o1 = (v.y-mu)*rs*(1.0f+md[Ff+f+1]) + md[f+1];
    float o2 = (v.z-mu)*rs*(1.0f+md[Ff+f+2]) + md[f+2];
    float o3 = (v.w-mu)*rs*(1.0f+md[Ff+f+3]) + md[f+3];
    fp16 h4[4] = {__float2half_rn(o0), __float2half_rn(o1),
                  __float2half_rn(o2), __float2half_rn(o3)};
    *(uint2*)&oh[(size_t)row*ld + f] = *(uint2*)h4;
}

// ---------------- HMMA GEMM: C[M,N] = A @ B^T  (fp16 in, fp32 accum) ----------
// 128x128 CTA tile, 8 warps of 64x32, K-chunk 64, 3-slot ring (one sync/chunk).
// Stage: A 16KB + B 16KB = 32KB; 3 slots = 96KB; 2 CTAs/SM.
__device__ __forceinline__ void load_stage(uint32_t b,
    const fp16* __restrict__ A, int lda, const fp16* __restrict__ B, int ldb,
    int m0, int n0, int kc, int tid) {
    #pragma unroll
    for (int i = 0; i < 4; i++) {
        int idx = tid + i*256;            // 0..1023: 128 rows x 8 chunks of 16B
        int row = idx >> 3, c16 = idx & 7;
        uint32_t o = sw64((uint32_t)(row*64 + (c16 & 3)*16)) + (uint32_t)(c16 >> 2)*8192u;
        // c16 0..3 -> first K-32 half (A rows), 4..7 -> second half layout:
        // layout: [A k0..31 8KB][A k32..63 8KB][B k0..31 8KB][B k32..63 8KB]? 
        // simpler: keep two 16KB halves per operand: A at 0, B at 16384.
        (void)o;
    }
    // A: 128 rows x 64 halves (2 x 32-K sub-tiles of 8KB each)
    #pragma unroll
    for (int i = 0; i < 2; i++) {
        int idx = tid + i*256;            // 0..511
        int row = idx >> 2, c16 = idx & 3;
        uint32_t o = sw64((uint32_t)(row*64 + c16*16));
        cpa16(b + o,         A + (size_t)(m0+row)*lda + kc + c16*8);
        cpa16(b + 8192 + o,  A + (size_t)(m0+row)*lda + kc + 32 + c16*8);
        cpa16(b + 16384 + o, B + (size_t)(n0+row)*ldb + kc + c16*8);
        cpa16(b + 24576 + o, B + (size_t)(n0+row)*ldb + kc + 32 + c16*8);
    }
}

// EPI: 0 fp32 C  1 x1=aux1+g1*(v+aux2)  2 gelu(v+aux2)->fp16  3 aux1+g2*(v+aux2)
template<int EPI>
__global__ __launch_bounds__(256, 2) void gemm_tc(
    const fp16* __restrict__ A, int lda,
    const fp16* __restrict__ B, int ldb, int K,
    float* __restrict__ C, int ldc, const float* __restrict__ aux1,
    const float* __restrict__ aux2, fp16* __restrict__ obh)
{
    extern __shared__ char dsm[];
    uint32_t sb = (s2u(dsm) + 1023u) & ~1023u;
    int tid = threadIdx.x;
    int n0 = blockIdx.x*128, m0 = blockIdx.y*128;
    int wid = tid>>5, lane = tid&31;
    int wm = wid>>2, wn = wid&3;

    float acc[4][4][4];
    #pragma unroll
    for (int a = 0; a < 4; a++)
        #pragma unroll
        for (int bq = 0; bq < 4; bq++)
            #pragma unroll
            for (int r = 0; r < 4; r++) acc[a][bq][r] = 0.0f;

    const int NC = K >> 6;
    load_stage(sb,          A, lda, B, ldb, m0, n0, 0,  tid); CPC();
    if (NC > 1) { load_stage(sb + 32768u, A, lda, B, ldb, m0, n0, 64, tid); CPC(); }

    uint32_t slot = 0;
    for (int c = 0; c < NC; c++) {
        if (c + 1 < NC) { CPW(1); } else { CPW(0); }
        __syncthreads();
        if (c + 2 < NC) {
            uint32_t ns = slot + 2; if (ns >= 3) ns -= 3;
            load_stage(sb + ns*32768u, A, lda, B, ldb, m0, n0, (c+2)<<6, tid);
            CPC();
        }
        uint32_t cur = sb + slot*32768u;
        #pragma unroll
        for (int ks4 = 0; ks4 < 4; ks4++) {
            uint32_t subA = cur + (uint32_t)(ks4 >> 1)*8192u;
            uint32_t subB = cur + 16384u + (uint32_t)(ks4 >> 1)*8192u;
            int ks = ks4 & 1;
            uint32_t af[4][4], bf[4][2];
            #pragma unroll
            for (int mt = 0; mt < 4; mt++) {
                int row = wm*64 + mt*16 + (lane & 15);
                int ch  = ks*2 + (lane >> 4);
                ldmx4(af[mt], subA + sw64((uint32_t)(row*64 + ch*16)));
            }
            #pragma unroll
            for (int bp = 0; bp < 2; bp++) {
                int mi = lane >> 3;
                int row = wn*32 + bp*16 + (mi >> 1)*8 + (lane & 7);
                int ch  = ks*2 + (mi & 1);
                uint32_t r[4];
                ldmx4(r, subB + sw64((uint32_t)(row*64 + ch*16)));
                bf[bp*2][0]=r[0]; bf[bp*2][1]=r[1]; bf[bp*2+1][0]=r[2]; bf[bp*2+1][1]=r[3];
            }
            #pragma unroll
            for (int mt = 0; mt < 4; mt++)
                #pragma unroll
                for (int nt = 0; nt < 4; nt++)
                    hmma(acc[mt][nt], af[mt], bf[nt]);
        }
        slot++; if (slot >= 3) slot = 0;
    }

    int g = lane >> 2, tig = lane & 3;
    #pragma unroll
    for (int mt = 0; mt < 4; mt++) {
        #pragma unroll
        for (int nt = 0; nt < 4; nt++) {
            int n = n0 + wn*32 + nt*8 + tig*2;
            #pragma unroll
            for (int half = 0; half < 2; half++) {
                int m = m0 + wm*64 + mt*16 + g + half*8;
                float v0 = acc[mt][nt][half*2+0], v1 = acc[mt][nt][half*2+1];
                if (EPI == 0) {
                    float2 o = {v0, v1};
                    *(float2*)&C[(size_t)m*ldc + n] = o;
                } else if (EPI == 1 || EPI == 3) {
                    int bb = m >> 13;
                    const float* md = d_mods + bb*(6*Ff) + (EPI==1 ? 2*Ff : 5*Ff);
                    float2 o;
                    o.x = aux1[(size_t)m*Ff + n+0] + md[n+0]*(v0 + aux2[n+0]);
                    o.y = aux1[(size_t)m*Ff + n+1] + md[n+1]*(v1 + aux2[n+1]);
                    *(float2*)&C[(size_t)m*ldc + n] = o;
                } else {
                    fp16 hp[2];
                    hp[0] = __float2half_rn(fast_gelu(v0 + aux2[n+0]));
                    hp[1] = __float2half_rn(fast_gelu(v1 + aux2[n+1]));
                    *(uint32_t*)&obh[(size_t)m*ldc + n] = *(uint32_t*)hp;
                }
            }
        }
    }
}

// ---------------- 3-phase scan over row-major Bu[32768][256] -----------------
__global__ __launch_bounds__(64) void scan_local_k() {
    int c = threadIdx.x, chunk = blockIdx.x, b = blockIdx.y, dir = blockIdx.z;
    int rc = dir ? 128+c : c, ic = rc+64;
    float2 a = d_abar[dir*64+c];
    float* p = d_bu + (size_t)(b*Ss + chunk*64)*256;
    float re[64], im[64];
    #pragma unroll
    for (int j = 0; j < 64; j++) {
        int s = dir ? 63-j : j;
        re[j] = p[s*256+rc]; im[j] = p[s*256+ic];
    }
    float xr = 0.0f, xi = 0.0f;
    #pragma unroll
    for (int j = 0; j < 64; j++) {
        float nr = a.x*xr - a.y*xi + re[j];
        float ni = a.x*xi + a.y*xr + im[j];
        xr = nr; xi = ni; re[j] = xr; im[j] = xi;
    }
    #pragma unroll
    for (int j = 0; j < 64; j++) {
        int s = dir ? 63-j : j;
        p[s*256+rc] = re[j]; p[s*256+ic] = im[j];
    }
    d_car[(((size_t)(b*2+dir))*128 + chunk)*64 + c] = make_float2(xr, xi);
}

__global__ void scan_combine_k() {
    int tid = threadIdx.x;
    int b = tid>>7, dir = (tid>>6)&1, c = tid&63;
    float2 a = d_abar[dir*64+c], a64 = a;
    #pragma unroll
    for (int i = 0; i < 6; i++) {
        float t = a64.x*a64.x - a64.y*a64.y;
        a64.y = 2.0f*a64.x*a64.y; a64.x = t;
    }
    size_t base = ((size_t)(b*2+dir))*128*64 + c;
    float ox = 0.0f, oy = 0.0f;
    for (int k = 0; k < 128; k++) {
        int ch = dir ? 127-k : k;
        float2 cr = d_car[base + (size_t)ch*64];
        d_off[base + (size_t)ch*64] = make_float2(ox, oy);
        float nx = a64.x*ox - a64.y*oy + cr.x;
        float ny = a64.x*oy + a64.y*ox + cr.y;
        ox = nx; oy = ny;
    }
}

__global__ __launch_bounds__(64) void scan_apply_k() {
    int c = threadIdx.x, chunk = blockIdx.x, b = blockIdx.y, dir = blockIdx.z;
    int rc = dir ? 128+c : c, ic = rc+64;
    float2 a = d_abar[dir*64+c];
    float2 O = d_off[(((size_t)(b*2+dir))*128 + chunk)*64 + c];
    const float* p = d_bu + (size_t)(b*Ss + chunk*64)*256;
    size_t rb = (size_t)(b*Ss + chunk*64);
    float px = a.x, py = a.y;
    #pragma unroll
    for (int j = 0; j < 64; j++) {
        int s = dir ? 63-j : j;
        float vr = p[s*256+rc] + (px*O.x - py*O.y);
        float vi = p[s*256+ic] + (px*O.y + py*O.x);
        float np = px*a.x - py*a.y;
        py = px*a.y + py*a.x; px = np;
        size_t ro = (rb + s)*KCB;
        d_comb[ro+rc] = __float2half_rn(vr);
        d_comb[ro+ic] = __float2half_rn(vi);
    }
}

// ---------------- launcher ----------------------------------------------------
extern "C" void kernel_launch(void* const* d_in, const int* in_sizes, int n_in,
                              void* d_out, int out_size) {
    const float* x      = (const float*)d_in[0];
    const float* cond   = (const float*)d_in[1];
    const float* f_la   = (const float*)d_in[2];
    const float* f_ai   = (const float*)d_in[3];
    const float* f_br   = (const float*)d_in[4];
    const float* f_bi   = (const float*)d_in[5];
    const float* f_cr   = (const float*)d_in[6];
    const float* f_ci   = (const float*)d_in[7];
    const float* f_d    = (const float*)d_in[8];
    const float* f_ld   = (const float*)d_in[9];
    const float* b_la   = (const float*)d_in[10];
    const float* b_ai   = (const float*)d_in[11];
    const float* b_br   = (const float*)d_in[12];
    const float* b_bi   = (const float*)d_in[13];
    const float* b_cr   = (const float*)d_in[14];
    const float* b_ci   = (const float*)d_in[15];
    const float* b_d    = (const float*)d_in[16];
    const float* b_ld   = (const float*)d_in[17];
    const float* proj_w = (const float*)d_in[18];
    const float* proj_b = (const float*)d_in[19];
    const float* ada_w  = (const float*)d_in[20];
    const float* ada_b  = (const float*)d_in[21];
    const float* mlp_w1 = (const float*)d_in[22];
    const float* mlp_b1 = (const float*)d_in[23];
    const float* mlp_w2 = (const float*)d_in[24];
    const float* mlp_b2 = (const float*)d_in[25];
    float* out = (float*)d_out;

    const int DSM = 3*32768 + 1024;
    cudaFuncSetAttribute(gemm_tc<0>, cudaFuncAttributeMaxDynamicSharedMemorySize, DSM);
    cudaFuncSetAttribute(gemm_tc<1>, cudaFuncAttributeMaxDynamicSharedMemorySize, DSM);
    cudaFuncSetAttribute(gemm_tc<2>, cudaFuncAttributeMaxDynamicSharedMemorySize, DSM);
    cudaFuncSetAttribute(gemm_tc<3>, cudaFuncAttributeMaxDynamicSharedMemorySize, DSM);

    float *bu, *x1; fp16 *comb, *h2, *g, *wbu, *wc, *w1, *w2;
    cudaGetSymbolAddress((void**)&bu, d_bu);
    cudaGetSymbolAddress((void**)&x1, d_x1);
    cudaGetSymbolAddress((void**)&comb, d_comb);
    cudaGetSymbolAddress((void**)&h2, d_h2);
    cudaGetSymbolAddress((void**)&g, d_g);
    cudaGetSymbolAddress((void**)&wbu, d_wbu);
    cudaGetSymbolAddress((void**)&wc, d_wc);
    cudaGetSymbolAddress((void**)&w1, d_w1);
    cudaGetSymbolAddress((void**)&w2, d_w2);

    prep_mods_k<<<dim3(12,4), 256>>>(cond, ada_w, ada_b);
    prep_ssm_k<<<128, 512>>>(f_la,f_ai,f_br,f_bi,f_ld, b_la,b_ai,b_br,b_bi,b_ld);
    prep_wc_k<<<768, 512>>>(f_cr, f_ci, b_cr, b_ci, f_d, b_d, proj_w);
    transpose_k<<<2048, 256>>>(mlp_w1, w1, mlp_w2, w2);
    ln_mod_k<<<BSr, 128>>>(x, comb+256, KCB, 0);

    // Bu[32768,256] = h @ Wbu^T
    gemm_tc<0><<<dim3(2,256), 256, DSM>>>(comb+256, KCB, wbu, Ff, Ff,
                                          bu, 256, nullptr, nullptr, nullptr);
    scan_local_k<<<dim3(128,4,2), 64>>>();
    scan_combine_k<<<1, 512>>>();
    scan_apply_k<<<dim3(128,4,2), 64>>>();

    // x1 = x + g1*(comb @ Wc^T + proj_b)
    gemm_tc<1><<<dim3(4,256), 256, DSM>>>(comb, KCB, wc, KCB, KCB,
                                          x1, Ff, x, proj_b, nullptr);

    // h2 = modulated LN(x1)
    ln_mod_k<<<BSr, 128>>>(x1, h2, Ff, 3*Ff);

    // g = gelu(h2 @ W1^T + b1) -> fp16
    gemm_tc<2><<<dim3(16,256), 256, DSM>>>(h2, Ff, w1, Ff, Ff,
                                           nullptr, Hh, nullptr, mlp_b1, g);

    // out = x1 + g2*(g @ W2^T + b2)
    gemm_tc<3><<<dim3(4,256), 256, DSM>>>(g, Hh, w2, Hh, Hh,
                                          out, Ff, x1, mlp_b2, nullptr);
}

// round 12
// speedup vs baseline: 1.2200x; 1.0463x over previous
#include <cuda_runtime.h>
#include <cuda_fp16.h>
#include <math.h>
#include <stdint.h>

#define Bb 4
#define Ss 8192
#define Ff 512
#define Hh 2048
#define BSr 32768
#define KCB 768
typedef __half fp16;

__device__ __align__(256) float  d_bu[(size_t)BSr*256];
__device__ __align__(256) fp16   d_comb[(size_t)BSr*KCB];   // cols 0..255 xs, 256..767 h
__device__ __align__(256) fp16   d_h2[(size_t)BSr*Ff];
__device__ __align__(256) fp16   d_g[(size_t)BSr*Hh];
__device__ __align__(256) float  d_x1[(size_t)BSr*Ff];
__device__ float  d_mods[Bb*6*Ff];
__device__ float2 d_abar[128];
__device__ float2 d_car[Bb*2*128*64];
__device__ __align__(256) fp16   d_wbu[256*Ff];
__device__ __align__(256) fp16   d_wc[Ff*KCB];
__device__ __align__(256) fp16   d_w1[(size_t)Hh*Ff];
__device__ __align__(256) fp16   d_w2[(size_t)Ff*Hh];

__device__ __forceinline__ uint32_t s2u(const void* p){
    uint32_t a;
    asm("{ .reg .u64 t; cvta.to.shared.u64 t, %1; cvt.u32.u64 %0, t; }":"=r"(a):"l"(p));
    return a;
}
__device__ __forceinline__ uint32_t sw64(uint32_t o){ return o ^ ((o >> 3) & 0x30u); }
__device__ __forceinline__ void cpa16(uint32_t d, const void* s){
    asm volatile("cp.async.cg.shared.global [%0], [%1], 16;"::"r"(d),"l"(s));
}
#define CPC() asm volatile("cp.async.commit_group;")
#define CPW(n) asm volatile("cp.async.wait_group %0;"::"n"(n))

__device__ __forceinline__ void ldmx4(uint32_t* r, uint32_t a){
    asm volatile("ldmatrix.sync.aligned.m8n8.x4.shared.b16 {%0,%1,%2,%3}, [%4];"
        :"=r"(r[0]),"=r"(r[1]),"=r"(r[2]),"=r"(r[3]):"r"(a));
}
__device__ __forceinline__ void hmma(float* d, const uint32_t* a, const uint32_t* b){
    asm volatile("mma.sync.aligned.m16n8k16.row.col.f32.f16.f16.f32 "
        "{%0,%1,%2,%3}, {%4,%5,%6,%7}, {%8,%9}, {%0,%1,%2,%3};"
        : "+f"(d[0]),"+f"(d[1]),"+f"(d[2]),"+f"(d[3])
        : "r"(a[0]),"r"(a[1]),"r"(a[2]),"r"(a[3]),"r"(b[0]),"r"(b[1]));
}
// gelu(tanh approx) == x * sigmoid(1.59577*(x + 0.044715 x^3))
__device__ __forceinline__ float fast_gelu(float x){
    float u = x*(1.0f + 0.044715f*x*x);
    float e = __expf(-1.5957691216057308f*u);
    return x * __frcp_rn(1.0f + e);
}

// ---------------- merged prep: blocks [0,768) wc | [768,896) ssm |
//                  [896,2944) transposes | [2944,2968) mods. 512 threads. ----
__global__ __launch_bounds__(512) void prep_all_k(
    const float* __restrict__ cond, const float* __restrict__ aw,
    const float* __restrict__ ab,
    const float* fla, const float* fai, const float* fbr, const float* fbi,
    const float* fld, const float* bla, const float* bai, const float* bbr,
    const float* bbi, const float* bld,
    const float* fcr, const float* fci, const float* bcr, const float* bci,
    const float* Df, const float* Db, const float* pw,
    const float* __restrict__ w1s, const float* __restrict__ w2s)
{
    int bid = blockIdx.x, tid = threadIdx.x;
    if (bid < 768) {
        if (bid < 256) {
            int ch = bid, blk = ch>>6, n = ch&63;
            const float* C = (blk==0)?fcr:(blk==1)?fci:(blk==2)?bcr:bci;
            float sign = (blk==1||blk==3)?-1.0f:1.0f;
            int poff = (blk>=2)?Ff:0;
            __shared__ float sC[Ff];
            sC[tid] = C[tid*64+n];
            __syncthreads();
            float acc = 0.0f;
            #pragma unroll 8
            for (int f = 0; f < Ff; f++) acc += sC[f]*pw[(poff+f)*Ff+tid];
            d_wc[(size_t)tid*KCB+ch] = __float2half_rn(sign*acc);
        } else {
            int idx = (bid - 256)*512 + tid;   // 0..262143
            int f = idx>>9, fp = idx&511;
            float v = Df[f]*pw[idx] + Db[f]*pw[idx+Ff*Ff];
            d_wc[(size_t)fp*KCB+256+f] = __float2half_rn(v);
        }
    } else if (bid < 896) {
        int id = bid - 768;
        int n = id & 63, dir = id >> 6;
        const float* la = dir?bla:fla; const float* ai = dir?bai:fai;
        const float* br = dir?bbr:fbr; const float* bi = dir?bbi:fbi;
        const float* ld = dir?bld:fld;
        float dt = expf(ld[n]), Are = -expf(la[n]), Aim = ai[n];
        float er = expf(Are*dt);
        float abr = er*cosf(Aim*dt), abi = er*sinf(Aim*dt);
        float dre = Are + 1e-8f, dim = Aim;
        float den = dre*dre + dim*dim;
        float nre = abr - 1.0f, nim = abi;
        float cre = (nre*dre + nim*dim)/den, cim = (nim*dre - nre*dim)/den;
        if (tid == 0) d_abar[dir*64+n] = make_float2(abr, abi);
        float bre = br[n*Ff+tid], bim = bi[n*Ff+tid];
        d_wbu[(dir*128+n)*Ff+tid]    = __float2half_rn(cre*bre - cim*bim);
        d_wbu[(dir*128+64+n)*Ff+tid] = __float2half_rn(cre*bim + cim*bre);
    } else if (bid < 2944) {
        int id = bid - 896;
        __shared__ float t[32][33];
        const float* s; fp16* d; int R, C, bx, by;
        if (id < 1024) { s = w1s; d = d_w1; R = Ff; C = Hh; bx = (id & 63)*32; by = (id >> 6)*32; }
        else { id -= 1024; s = w2s; d = d_w2; R = Hh; C = Ff; bx = (id & 15)*32; by = (id >> 4)*32; }
        int tx = tid & 31, ty = tid >> 5;   // ty 0..15
        #pragma unroll
        for (int i = 0; i < 32; i += 16) t[ty+i][tx] = s[(size_t)(by+ty+i)*C + bx+tx];
        __syncthreads();
        #pragma unroll
        for (int i = 0; i < 32; i += 16)
            d[(size_t)(bx+ty+i)*R + by+tx] = __float2half_rn(t[tx][ty+i]);
    } else {
        int id = bid - 2944;              // 0..23
        int b = id / 6, seg = id % 6;
        __shared__ float sc[Ff];
        sc[tid] = 0.0f;
        float v = cond[b*Ff + tid];
        sc[tid] = v * __frcp_rn(1.0f + __expf(-v));
        __syncthreads();
        int j = seg*512 + tid;            // 0..3071
        float acc = ab[j];
        #pragma unroll 8
        for (int f = 0; f < Ff; f++) acc += sc[f]*aw[f*(6*Ff)+j];
        d_mods[b*(6*Ff)+j] = acc;
    }
}

__global__ void ln_mod_k(const float* __restrict__ in, fp16* __restrict__ oh,
                         int ld, int moff) {
    int row = blockIdx.x, bb = row>>13, tid = threadIdx.x;
    float4 v = ((const float4*)(in + (size_t)row*Ff))[tid];
    float s = v.x+v.y+v.z+v.w, sq = v.x*v.x+v.y*v.y+v.z*v.z+v.w*v.w;
    #pragma unroll
    for (int o = 16; o > 0; o >>= 1) {
        s += __shfl_down_sync(~0u, s, o); sq += __shfl_down_sync(~0u, sq, o);
    }
    __shared__ float ss[4], sv[4];
    int w = tid>>5, l = tid&31;
    if (l==0){ ss[w]=s; sv[w]=sq; }
    __syncthreads();
    if (tid==0){ ss[0]+=ss[1]+ss[2]+ss[3]; sv[0]+=sv[1]+sv[2]+sv[3]; }
    __syncthreads();
    float mu = ss[0]*(1.0f/512.0f), var = sv[0]*(1.0f/512.0f) - mu*mu;
    float rs = rsqrtf(var + 1e-5f);
    const float* md = d_mods + bb*(6*Ff) + moff;
    int f = tid*4;
    float o0 = (v.x-mu)*rs*(1.0f+md[Ff+f+0]) + md[f+0];
    float o1 = (v.y-mu)*rs*(1.0f+md[Ff+f+1]) + md[f+1];
    float o2 = (v.z-mu)*rs*(1.0f+md[Ff+f+2]) + md[f+2];
    float o3 = (v.w-mu)*rs*(1.0f+md[Ff+f+3]) + md[f+3];
    fp16 h4[4] = {__float2half_rn(o0), __float2half_rn(o1),
                  __float2half_rn(o2), __float2half_rn(o3)};
    *(uint2*)&oh[(size_t)row*ld + f] = *(uint2*)h4;
}

// ---------------- HMMA GEMM (R7 champion config) ------------------------------
// 128x128 CTA tile, 8 warps of 64x32, K-chunk 64 (two 16KB sub-stages),
// double-buffered cp.async: stage = 32KB.
__device__ __forceinline__ void load_sub(uint32_t b,
    const fp16* __restrict__ A, int lda, const fp16* __restrict__ B, int ldb,
    int m0, int n0, int kc, int tid) {
    #pragma unroll
    for (int i = 0; i < 2; i++) {
        int idx = tid + i*256;            // 0..511
        int row = idx >> 2, c16 = idx & 3;
        uint32_t o = sw64((uint32_t)(row*64 + c16*16));
        cpa16(b + o,        A + (size_t)(m0+row)*lda + kc + c16*8);
        cpa16(b + 8192 + o, B + (size_t)(n0+row)*ldb + kc + c16*8);
    }
}
__device__ __forceinline__ void load_stage(uint32_t b,
    const fp16* __restrict__ A, int lda, const fp16* __restrict__ B, int ldb,
    int m0, int n0, int kc, int tid) {
    load_sub(b,         A, lda, B, ldb, m0, n0, kc,      tid);
    load_sub(b + 16384, A, lda, B, ldb, m0, n0, kc + 32, tid);
}

// EPI: 0 fp32 C  1 x1=aux1+g1*(v+aux2)  2 gelu(v+aux2)->fp16  3 aux1+g2*(v+aux2)
template<int EPI>
__global__ __launch_bounds__(256, 2) void gemm_tc(
    const fp16* __restrict__ A, int lda,
    const fp16* __restrict__ B, int ldb, int K,
    float* __restrict__ C, int ldc, const float* __restrict__ aux1,
    const float* __restrict__ aux2, fp16* __restrict__ obh)
{
    extern __shared__ char dsm[];
    uint32_t sb = (s2u(dsm) + 1023u) & ~1023u;
    int tid = threadIdx.x;
    int n0 = blockIdx.x*128, m0 = blockIdx.y*128;
    int wid = tid>>5, lane = tid&31;
    int wm = wid>>2, wn = wid&3;

    float acc[4][4][4];
    #pragma unroll
    for (int a = 0; a < 4; a++)
        #pragma unroll
        for (int bq = 0; bq < 4; bq++)
            #pragma unroll
            for (int r = 0; r < 4; r++) acc[a][bq][r] = 0.0f;

    const int NC = K >> 6;
    load_stage(sb, A, lda, B, ldb, m0, n0, 0, tid);
    CPC();
    for (int c = 0; c < NC; c++) {
        uint32_t cur = sb + (uint32_t)(c & 1)*32768u;
        if (c + 1 < NC) {
            load_stage(sb + (uint32_t)((c+1)&1)*32768u, A, lda, B, ldb,
                       m0, n0, (c+1)<<6, tid);
            CPC();
            CPW(1);
        } else {
            CPW(0);
        }
        __syncthreads();
        #pragma unroll
        for (int ks4 = 0; ks4 < 4; ks4++) {
            uint32_t sub = cur + (uint32_t)(ks4 >> 1)*16384u;
            int ks = ks4 & 1;
            uint32_t af[4][4], bf[4][2];
            #pragma unroll
            for (int mt = 0; mt < 4; mt++) {
                int row = wm*64 + mt*16 + (lane & 15);
                int ch  = ks*2 + (lane >> 4);
                ldmx4(af[mt], sub + sw64((uint32_t)(row*64 + ch*16)));
            }
            #pragma unroll
            for (int bp = 0; bp < 2; bp++) {
                int mi = lane >> 3;
                int row = wn*32 + bp*16 + (mi >> 1)*8 + (lane & 7);
                int ch  = ks*2 + (mi & 1);
                uint32_t r[4];
                ldmx4(r, sub + 8192 + sw64((uint32_t)(row*64 + ch*16)));
                bf[bp*2][0]=r[0]; bf[bp*2][1]=r[1]; bf[bp*2+1][0]=r[2]; bf[bp*2+1][1]=r[3];
            }
            #pragma unroll
            for (int mt = 0; mt < 4; mt++)
                #pragma unroll
                for (int nt = 0; nt < 4; nt++)
                    hmma(acc[mt][nt], af[mt], bf[nt]);
        }
        __syncthreads();
    }

    int g = lane >> 2, tig = lane & 3;
    #pragma unroll
    for (int mt = 0; mt < 4; mt++) {
        #pragma unroll
        for (int nt = 0; nt < 4; nt++) {
            int n = n0 + wn*32 + nt*8 + tig*2;
            #pragma unroll
            for (int half = 0; half < 2; half++) {
                int m = m0 + wm*64 + mt*16 + g + half*8;
                float v0 = acc[mt][nt][half*2+0], v1 = acc[mt][nt][half*2+1];
                if (EPI == 0) {
                    float2 o = {v0, v1};
                    *(float2*)&C[(size_t)m*ldc + n] = o;
                } else if (EPI == 1 || EPI == 3) {
                    int bb = m >> 13;
                    const float* md = d_mods + bb*(6*Ff) + (EPI==1 ? 2*Ff : 5*Ff);
                    float2 o;
                    o.x = aux1[(size_t)m*Ff + n+0] + md[n+0]*(v0 + aux2[n+0]);
                    o.y = aux1[(size_t)m*Ff + n+1] + md[n+1]*(v1 + aux2[n+1]);
                    *(float2*)&C[(size_t)m*ldc + n] = o;
                } else {
                    fp16 hp[2];
                    hp[0] = __float2half_rn(fast_gelu(v0 + aux2[n+0]));
                    hp[1] = __float2half_rn(fast_gelu(v1 + aux2[n+1]));
                    *(uint32_t*)&obh[(size_t)m*ldc + n] = *(uint32_t*)hp;
                }
            }
        }
    }
}

// ---------------- scan over row-major Bu[32768][256]: 2 kernels --------------
__global__ __launch_bounds__(64) void scan_local_k() {
    int c = threadIdx.x, chunk = blockIdx.x, b = blockIdx.y, dir = blockIdx.z;
    int rc = dir ? 128+c : c, ic = rc+64;
    float2 a = d_abar[dir*64+c];
    float* p = d_bu + (size_t)(b*Ss + chunk*64)*256;
    float re[64], im[64];
    #pragma unroll
    for (int j = 0; j < 64; j++) {
        int s = dir ? 63-j : j;
        re[j] = p[s*256+rc]; im[j] = p[s*256+ic];
    }
    float xr = 0.0f, xi = 0.0f;
    #pragma unroll
    for (int j = 0; j < 64; j++) {
        float nr = a.x*xr - a.y*xi + re[j];
        float ni = a.x*xi + a.y*xr + im[j];
        xr = nr; xi = ni; re[j] = xr; im[j] = xi;
    }
    #pragma unroll
    for (int j = 0; j < 64; j++) {
        int s = dir ? 63-j : j;
        p[s*256+rc] = re[j]; p[s*256+ic] = im[j];
    }
    d_car[(((size_t)(b*2+dir))*128 + chunk)*64 + c] = make_float2(xr, xi);
}

// apply: compute own chunk-prefix from d_car inline, then add carries + emit fp16
__global__ __launch_bounds__(64) void scan_apply_k() {
    int c = threadIdx.x, chunk = blockIdx.x, b = blockIdx.y, dir = blockIdx.z;
    int rc = dir ? 128+c : c, ic = rc+64;
    float2 a = d_abar[dir*64+c];
    float2 a64 = a;
    #pragma unroll
    for (int i = 0; i < 6; i++) {
        float t = a64.x*a64.x - a64.y*a64.y;
        a64.y = 2.0f*a64.x*a64.y; a64.x = t;
    }
    size_t base = ((size_t)(b*2+dir))*128*64 + c;
    float ox = 0.0f, oy = 0.0f;
    if (!dir) {
        for (int ch = 0; ch < chunk; ch++) {
            float2 cr = d_car[base + (size_t)ch*64];
            float nx = a64.x*ox - a64.y*oy + cr.x;
            float ny = a64.x*oy + a64.y*ox + cr.y;
            ox = nx; oy = ny;
        }
    } else {
        for (int ch = 127; ch > chunk; ch--) {
            float2 cr = d_car[base + (size_t)ch*64];
            float nx = a64.x*ox - a64.y*oy + cr.x;
            float ny = a64.x*oy + a64.y*ox + cr.y;
            ox = nx; oy = ny;
        }
    }
    const float* p = d_bu + (size_t)(b*Ss + chunk*64)*256;
    size_t rb = (size_t)(b*Ss + chunk*64);
    float px = a.x, py = a.y;
    #pragma unroll
    for (int j = 0; j < 64; j++) {
        int s = dir ? 63-j : j;
        float vr = p[s*256+rc] + (px*ox - py*oy);
        float vi = p[s*256+ic] + (px*oy + py*ox);
        float np = px*a.x - py*a.y;
        py = px*a.y + py*a.x; px = np;
        size_t ro = (rb + s)*KCB;
        d_comb[ro+rc] = __float2half_rn(vr);
        d_comb[ro+ic] = __float2half_rn(vi);
    }
}

// ---------------- launcher ----------------------------------------------------
extern "C" void kernel_launch(void* const* d_in, const int* in_sizes, int n_in,
                              void* d_out, int out_size) {
    const float* x      = (const float*)d_in[0];
    const float* cond   = (const float*)d_in[1];
    const float* f_la   = (const float*)d_in[2];
    const float* f_ai   = (const float*)d_in[3];
    const float* f_br   = (const float*)d_in[4];
    const float* f_bi   = (const float*)d_in[5];
    const float* f_cr   = (const float*)d_in[6];
    const float* f_ci   = (const float*)d_in[7];
    const float* f_d    = (const float*)d_in[8];
    const float* f_ld   = (const float*)d_in[9];
    const float* b_la   = (const float*)d_in[10];
    const float* b_ai   = (const float*)d_in[11];
    const float* b_br   = (const float*)d_in[12];
    const float* b_bi   = (const float*)d_in[13];
    const float* b_cr   = (const float*)d_in[14];
    const float* b_ci   = (const float*)d_in[15];
    const float* b_d    = (const float*)d_in[16];
    const float* b_ld   = (const float*)d_in[17];
    const float* proj_w = (const float*)d_in[18];
    const float* proj_b = (const float*)d_in[19];
    const float* ada_w  = (const float*)d_in[20];
    const float* ada_b  = (const float*)d_in[21];
    const float* mlp_w1 = (const float*)d_in[22];
    const float* mlp_b1 = (const float*)d_in[23];
    const float* mlp_w2 = (const float*)d_in[24];
    const float* mlp_b2 = (const float*)d_in[25];
    float* out = (float*)d_out;

    const int DSM = 2*32768 + 1024;
    cudaFuncSetAttribute(gemm_tc<0>, cudaFuncAttributeMaxDynamicSharedMemorySize, DSM);
    cudaFuncSetAttribute(gemm_tc<1>, cudaFuncAttributeMaxDynamicSharedMemorySize, DSM);
    cudaFuncSetAttribute(gemm_tc<2>, cudaFuncAttributeMaxDynamicSharedMemorySize, DSM);
    cudaFuncSetAttribute(gemm_tc<3>, cudaFuncAttributeMaxDynamicSharedMemorySize, DSM);

    float *bu, *x1; fp16 *comb, *h2, *g, *wbu, *wc, *w1, *w2;
    cudaGetSymbolAddress((void**)&bu, d_bu);
    cudaGetSymbolAddress((void**)&x1, d_x1);
    cudaGetSymbolAddress((void**)&comb, d_comb);
    cudaGetSymbolAddress((void**)&h2, d_h2);
    cudaGetSymbolAddress((void**)&g, d_g);
    cudaGetSymbolAddress((void**)&wbu, d_wbu);
    cudaGetSymbolAddress((void**)&wc, d_wc);
    cudaGetSymbolAddress((void**)&w1, d_w1);
    cudaGetSymbolAddress((void**)&w2, d_w2);

    // 1: merged prep (wc | ssm | transposes | mods)
    prep_all_k<<<2968, 512>>>(cond, ada_w, ada_b,
                              f_la, f_ai, f_br, f_bi, f_ld,
                              b_la, b_ai, b_br, b_bi, b_ld,
                              f_cr, f_ci, b_cr, b_ci, f_d, b_d, proj_w,
                              mlp_w1, mlp_w2);

    // 2: h = modulated LN(x) -> comb cols 256..767
    ln_mod_k<<<BSr, 128>>>(x, comb+256, KCB, 0);

    // 3: Bu[32768,256] = h @ Wbu^T
    gemm_tc<0><<<dim3(2,256), 256, DSM>>>(comb+256, KCB, wbu, Ff, Ff,
                                          bu, 256, nullptr, nullptr, nullptr);
    // 4-5: scan
    scan_local_k<<<dim3(128,4,2), 64>>>();
    scan_apply_k<<<dim3(128,4,2), 64>>>();

    // 6: x1 = x + g1*(comb @ Wc^T + proj_b)
    gemm_tc<1><<<dim3(4,256), 256, DSM>>>(comb, KCB, wc, KCB, KCB,
                                          x1, Ff, x, proj_b, nullptr);

    // 7: h2 = modulated LN(x1)
    ln_mod_k<<<BSr, 128>>>(x1, h2, Ff, 3*Ff);

    // 8: g = gelu(h2 @ W1^T + b1) -> fp16
    gemm_tc<2><<<dim3(16,256), 256, DSM>>>(h2, Ff, w1, Ff, Ff,
                                           nullptr, Hh, nullptr, mlp_b1, g);

    // 9: out = x1 + g2*(g @ W2^T + b2)
    gemm_tc<3><<<dim3(4,256), 256, DSM>>>(g, Hh, w2, Hh, Hh,
                                          out, Ff, x1, mlp_b2, nullptr);
}

// round 13
// speedup vs baseline: 1.2327x; 1.0104x over previous
#include <cuda_runtime.h>
#include <cuda_fp16.h>
#include <math.h>
#include <stdint.h>

#define Bb 4
#define Ss 8192
#define Ff 512
#define Hh 2048
#define BSr 32768
#define KCB 768
typedef __half fp16;

__device__ __align__(256) float  d_bu[(size_t)BSr*256];
__device__ __align__(256) fp16   d_comb[(size_t)BSr*KCB];   // cols 0..255 xs, 256..767 h
__device__ __align__(256) fp16   d_h2[(size_t)BSr*Ff];
__device__ __align__(256) fp16   d_g[(size_t)BSr*Hh];
__device__ __align__(256) float  d_x1[(size_t)BSr*Ff];
__device__ float  d_mods[Bb*6*Ff];
__device__ float2 d_abar[128];
__device__ float2 d_car[Bb*2*128*64];
__device__ __align__(256) fp16   d_wbu[256*Ff];
__device__ __align__(256) fp16   d_wc[Ff*KCB];
__device__ __align__(256) fp16   d_w1[(size_t)Hh*Ff];
__device__ __align__(256) fp16   d_w2[(size_t)Ff*Hh];

__device__ __forceinline__ uint32_t s2u(const void* p){
    uint32_t a;
    asm("{ .reg .u64 t; cvta.to.shared.u64 t, %1; cvt.u32.u64 %0, t; }":"=r"(a):"l"(p));
    return a;
}
__device__ __forceinline__ uint32_t sw64(uint32_t o){ return o ^ ((o >> 3) & 0x30u); }
__device__ __forceinline__ void cpa16(uint32_t d, const void* s){
    asm volatile("cp.async.cg.shared.global [%0], [%1], 16;"::"r"(d),"l"(s));
}
#define CPC() asm volatile("cp.async.commit_group;")
#define CPW(n) asm volatile("cp.async.wait_group %0;"::"n"(n))

__device__ __forceinline__ void ldmx4(uint32_t* r, uint32_t a){
    asm volatile("ldmatrix.sync.aligned.m8n8.x4.shared.b16 {%0,%1,%2,%3}, [%4];"
        :"=r"(r[0]),"=r"(r[1]),"=r"(r[2]),"=r"(r[3]):"r"(a));
}
__device__ __forceinline__ void hmma(float* d, const uint32_t* a, const uint32_t* b){
    asm volatile("mma.sync.aligned.m16n8k16.row.col.f32.f16.f16.f32 "
        "{%0,%1,%2,%3}, {%4,%5,%6,%7}, {%8,%9}, {%0,%1,%2,%3};"
        : "+f"(d[0]),"+f"(d[1]),"+f"(d[2]),"+f"(d[3])
        : "r"(a[0]),"r"(a[1]),"r"(a[2]),"r"(a[3]),"r"(b[0]),"r"(b[1]));
}
// gelu(tanh approx) == x * sigmoid(1.59577*(x + 0.044715 x^3))
__device__ __forceinline__ float fast_gelu(float x){
    float u = x*(1.0f + 0.044715f*x*x);
    float e = __expf(-1.5957691216057308f*u);
    return x * __frcp_rn(1.0f + e);
}

// ---------------- merged prep: blocks [0,768) wc | [768,896) ssm |
//                  [896,2944) transposes | [2944,2968) mods. 512 threads. ----
__global__ __launch_bounds__(512) void prep_all_k(
    const float* __restrict__ cond, const float* __restrict__ aw,
    const float* __restrict__ ab,
    const float* fla, const float* fai, const float* fbr, const float* fbi,
    const float* fld, const float* bla, const float* bai, const float* bbr,
    const float* bbi, const float* bld,
    const float* fcr, const float* fci, const float* bcr, const float* bci,
    const float* Df, const float* Db, const float* pw,
    const float* __restrict__ w1s, const float* __restrict__ w2s)
{
    int bid = blockIdx.x, tid = threadIdx.x;
    if (bid < 768) {
        if (bid < 256) {
            int ch = bid, blk = ch>>6, n = ch&63;
            const float* C = (blk==0)?fcr:(blk==1)?fci:(blk==2)?bcr:bci;
            float sign = (blk==1||blk==3)?-1.0f:1.0f;
            int poff = (blk>=2)?Ff:0;
            __shared__ float sC[Ff];
            sC[tid] = C[tid*64+n];
            __syncthreads();
            float acc = 0.0f;
            #pragma unroll 8
            for (int f = 0; f < Ff; f++) acc += sC[f]*pw[(poff+f)*Ff+tid];
            d_wc[(size_t)tid*KCB+ch] = __float2half_rn(sign*acc);
        } else {
            int idx = (bid - 256)*512 + tid;   // 0..262143
            int f = idx>>9, fp = idx&511;
            float v = Df[f]*pw[idx] + Db[f]*pw[idx+Ff*Ff];
            d_wc[(size_t)fp*KCB+256+f] = __float2half_rn(v);
        }
    } else if (bid < 896) {
        int id = bid - 768;
        int n = id & 63, dir = id >> 6;
        const float* la = dir?bla:fla; const float* ai = dir?bai:fai;
        const float* br = dir?bbr:fbr; const float* bi = dir?bbi:fbi;
        const float* ld = dir?bld:fld;
        float dt = expf(ld[n]), Are = -expf(la[n]), Aim = ai[n];
        float er = expf(Are*dt);
        float abr = er*cosf(Aim*dt), abi = er*sinf(Aim*dt);
        float dre = Are + 1e-8f, dim = Aim;
        float den = dre*dre + dim*dim;
        float nre = abr - 1.0f, nim = abi;
        float cre = (nre*dre + nim*dim)/den, cim = (nim*dre - nre*dim)/den;
        if (tid == 0) d_abar[dir*64+n] = make_float2(abr, abi);
        float bre = br[n*Ff+tid], bim = bi[n*Ff+tid];
        d_wbu[(dir*128+n)*Ff+tid]    = __float2half_rn(cre*bre - cim*bim);
        d_wbu[(dir*128+64+n)*Ff+tid] = __float2half_rn(cre*bim + cim*bre);
    } else if (bid < 2944) {
        int id = bid - 896;
        __shared__ float t[32][33];
        const float* s; fp16* d; int R, C, bx, by;
        if (id < 1024) { s = w1s; d = d_w1; R = Ff; C = Hh; bx = (id & 63)*32; by = (id >> 6)*32; }
        else { id -= 1024; s = w2s; d = d_w2; R = Hh; C = Ff; bx = (id & 15)*32; by = (id >> 4)*32; }
        int tx = tid & 31, ty = tid >> 5;   // ty 0..15
        #pragma unroll
        for (int i = 0; i < 32; i += 16) t[ty+i][tx] = s[(size_t)(by+ty+i)*C + bx+tx];
        __syncthreads();
        #pragma unroll
        for (int i = 0; i < 32; i += 16)
            d[(size_t)(bx+ty+i)*R + by+tx] = __float2half_rn(t[tx][ty+i]);
    } else {
        int id = bid - 2944;              // 0..23
        int b = id / 6, seg = id % 6;
        __shared__ float sc[Ff];
        sc[tid] = 0.0f;
        float v = cond[b*Ff + tid];
        sc[tid] = v * __frcp_rn(1.0f + __expf(-v));
        __syncthreads();
        int j = seg*512 + tid;            // 0..3071
        float acc = ab[j];
        #pragma unroll 8
        for (int f = 0; f < Ff; f++) acc += sc[f]*aw[f*(6*Ff)+j];
        d_mods[b*(6*Ff)+j] = acc;
    }
}

__global__ void ln_mod_k(const float* __restrict__ in, fp16* __restrict__ oh,
                         int ld, int moff) {
    int row = blockIdx.x, bb = row>>13, tid = threadIdx.x;
    float4 v = ((const float4*)(in + (size_t)row*Ff))[tid];
    float s = v.x+v.y+v.z+v.w, sq = v.x*v.x+v.y*v.y+v.z*v.z+v.w*v.w;
    #pragma unroll
    for (int o = 16; o > 0; o >>= 1) {
        s += __shfl_down_sync(~0u, s, o); sq += __shfl_down_sync(~0u, sq, o);
    }
    __shared__ float ss[4], sv[4];
    int w = tid>>5, l = tid&31;
    if (l==0){ ss[w]=s; sv[w]=sq; }
    __syncthreads();
    if (tid==0){ ss[0]+=ss[1]+ss[2]+ss[3]; sv[0]+=sv[1]+sv[2]+sv[3]; }
    __syncthreads();
    float mu = ss[0]*(1.0f/512.0f), var = sv[0]*(1.0f/512.0f) - mu*mu;
    float rs = rsqrtf(var + 1e-5f);
    const float* md = d_mods + bb*(6*Ff) + moff;
    int f = tid*4;
    float o0 = (v.x-mu)*rs*(1.0f+md[Ff+f+0]) + md[f+0];
    float o1 = (v.y-mu)*rs*(1.0f+md[Ff+f+1]) + md[f+1];
    float o2 = (v.z-mu)*rs*(1.0f+md[Ff+f+2]) + md[f+2];
    float o3 = (v.w-mu)*rs*(1.0f+md[Ff+f+3]) + md[f+3];
    fp16 h4[4] = {__float2half_rn(o0), __float2half_rn(o1),
                  __float2half_rn(o2), __float2half_rn(o3)};
    *(uint2*)&oh[(size_t)row*ld + f] = *(uint2*)h4;
}

// ---------------- HMMA GEMM (R7 champion config) ------------------------------
__device__ __forceinline__ void load_sub(uint32_t b,
    const fp16* __restrict__ A, int lda, const fp16* __restrict__ B, int ldb,
    int m0, int n0, int kc, int tid) {
    #pragma unroll
    for (int i = 0; i < 2; i++) {
        int idx = tid + i*256;            // 0..511
        int row = idx >> 2, c16 = idx & 3;
        uint32_t o = sw64((uint32_t)(row*64 + c16*16));
        cpa16(b + o,        A + (size_t)(m0+row)*lda + kc + c16*8);
        cpa16(b + 8192 + o, B + (size_t)(n0+row)*ldb + kc + c16*8);
    }
}
__device__ __forceinline__ void load_stage(uint32_t b,
    const fp16* __restrict__ A, int lda, const fp16* __restrict__ B, int ldb,
    int m0, int n0, int kc, int tid) {
    load_sub(b,         A, lda, B, ldb, m0, n0, kc,      tid);
    load_sub(b + 16384, A, lda, B, ldb, m0, n0, kc + 32, tid);
}

// EPI: 0 fp32 C  1 x1=aux1+g1*(v+aux2)  2 gelu(v+aux2)->fp16  3 aux1+g2*(v+aux2)
template<int EPI>
__global__ __launch_bounds__(256, 2) void gemm_tc(
    const fp16* __restrict__ A, int lda,
    const fp16* __restrict__ B, int ldb, int K,
    float* __restrict__ C, int ldc, const float* __restrict__ aux1,
    const float* __restrict__ aux2, fp16* __restrict__ obh)
{
    extern __shared__ char dsm[];
    uint32_t sb = (s2u(dsm) + 1023u) & ~1023u;
    int tid = threadIdx.x;
    int n0 = blockIdx.x*128, m0 = blockIdx.y*128;
    int wid = tid>>5, lane = tid&31;
    int wm = wid>>2, wn = wid&3;

    float acc[4][4][4];
    #pragma unroll
    for (int a = 0; a < 4; a++)
        #pragma unroll
        for (int bq = 0; bq < 4; bq++)
            #pragma unroll
            for (int r = 0; r < 4; r++) acc[a][bq][r] = 0.0f;

    const int NC = K >> 6;
    load_stage(sb, A, lda, B, ldb, m0, n0, 0, tid);
    CPC();
    for (int c = 0; c < NC; c++) {
        uint32_t cur = sb + (uint32_t)(c & 1)*32768u;
        if (c + 1 < NC) {
            load_stage(sb + (uint32_t)((c+1)&1)*32768u, A, lda, B, ldb,
                       m0, n0, (c+1)<<6, tid);
            CPC();
            CPW(1);
        } else {
            CPW(0);
        }
        __syncthreads();
        #pragma unroll
        for (int ks4 = 0; ks4 < 4; ks4++) {
            uint32_t sub = cur + (uint32_t)(ks4 >> 1)*16384u;
            int ks = ks4 & 1;
            uint32_t af[4][4], bf[4][2];
            #pragma unroll
            for (int mt = 0; mt < 4; mt++) {
                int row = wm*64 + mt*16 + (lane & 15);
                int ch  = ks*2 + (lane >> 4);
                ldmx4(af[mt], sub + sw64((uint32_t)(row*64 + ch*16)));
            }
            #pragma unroll
            for (int bp = 0; bp < 2; bp++) {
                int mi = lane >> 3;
                int row = wn*32 + bp*16 + (mi >> 1)*8 + (lane & 7);
                int ch  = ks*2 + (mi & 1);
                uint32_t r[4];
                ldmx4(r, sub + 8192 + sw64((uint32_t)(row*64 + ch*16)));
                bf[bp*2][0]=r[0]; bf[bp*2][1]=r[1]; bf[bp*2+1][0]=r[2]; bf[bp*2+1][1]=r[3];
            }
            #pragma unroll
            for (int mt = 0; mt < 4; mt++)
                #pragma unroll
                for (int nt = 0; nt < 4; nt++)
                    hmma(acc[mt][nt], af[mt], bf[nt]);
        }
        __syncthreads();
    }

    int g = lane >> 2, tig = lane & 3;
    #pragma unroll
    for (int mt = 0; mt < 4; mt++) {
        #pragma unroll
        for (int nt = 0; nt < 4; nt++) {
            int n = n0 + wn*32 + nt*8 + tig*2;
            #pragma unroll
            for (int half = 0; half < 2; half++) {
                int m = m0 + wm*64 + mt*16 + g + half*8;
                float v0 = acc[mt][nt][half*2+0], v1 = acc[mt][nt][half*2+1];
                if (EPI == 0) {
                    float2 o = {v0, v1};
                    *(float2*)&C[(size_t)m*ldc + n] = o;
                } else if (EPI == 1 || EPI == 3) {
                    int bb = m >> 13;
                    const float* md = d_mods + bb*(6*Ff) + (EPI==1 ? 2*Ff : 5*Ff);
                    float2 o;
                    o.x = aux1[(size_t)m*Ff + n+0] + md[n+0]*(v0 + aux2[n+0]);
                    o.y = aux1[(size_t)m*Ff + n+1] + md[n+1]*(v1 + aux2[n+1]);
                    *(float2*)&C[(size_t)m*ldc + n] = o;
                } else {
                    fp16 hp[2];
                    hp[0] = __float2half_rn(fast_gelu(v0 + aux2[n+0]));
                    hp[1] = __float2half_rn(fast_gelu(v1 + aux2[n+1]));
                    *(uint32_t*)&obh[(size_t)m*ldc + n] = *(uint32_t*)hp;
                }
            }
        }
    }
}

// ---------------- streaming scan: 2 passes, no register arrays ----------------
// pass 1: chunk carries only (read-only streaming over d_bu).
// fwd carry = sequential x=a*x+u (s ascending); rev carry = sum a^s u_s,
// also streamed s-ascending with a running power.
__global__ __launch_bounds__(256) void scan_carry_k() {
    int t = threadIdx.x;
    int c = t & 63;
    int chunk = blockIdx.x*4 + (t>>6);
    int b = blockIdx.y, dir = blockIdx.z;
    int rc = dir ? 128+c : c, ic = rc+64;
    float2 a = d_abar[dir*64+c];
    const float* p = d_bu + (size_t)(b*Ss + chunk*64)*256;
    float xr = 0.0f, xi = 0.0f;
    if (!dir) {
        for (int s = 0; s < 64; s++) {
            float ur = p[s*256+rc], ui = p[s*256+ic];
            float nr = a.x*xr - a.y*xi + ur;
            float ni = a.x*xi + a.y*xr + ui;
            xr = nr; xi = ni;
        }
    } else {
        float px = 1.0f, py = 0.0f;
        for (int s = 0; s < 64; s++) {
            float ur = p[s*256+rc], ui = p[s*256+ic];
            xr += px*ur - py*ui;
            xi += px*ui + py*ur;
            float np = px*a.x - py*a.y;
            py = px*a.y + py*a.x; px = np;
        }
    }
    d_car[(((size_t)(b*2+dir))*128 + chunk)*64 + c] = make_float2(xr, xi);
}

// pass 2: per-chunk prefix from d_car, then streaming apply writing fp16 comb
__global__ __launch_bounds__(256) void scan_apply_k() {
    int t = threadIdx.x;
    int c = t & 63;
    int chunk = blockIdx.x*4 + (t>>6);
    int b = blockIdx.y, dir = blockIdx.z;
    int rc = dir ? 128+c : c, ic = rc+64;
    float2 a = d_abar[dir*64+c];
    float2 a64 = a;
    #pragma unroll
    for (int i = 0; i < 6; i++) {
        float tq = a64.x*a64.x - a64.y*a64.y;
        a64.y = 2.0f*a64.x*a64.y; a64.x = tq;
    }
    size_t base = ((size_t)(b*2+dir))*128*64 + c;
    float ox = 0.0f, oy = 0.0f;
    if (!dir) {
        for (int ch = 0; ch < chunk; ch++) {
            float2 cr = d_car[base + (size_t)ch*64];
            float nx = a64.x*ox - a64.y*oy + cr.x;
            float ny = a64.x*oy + a64.y*ox + cr.y;
            ox = nx; oy = ny;
        }
    } else {
        for (int ch = 127; ch > chunk; ch--) {
            float2 cr = d_car[base + (size_t)ch*64];
            float nx = a64.x*ox - a64.y*oy + cr.x;
            float ny = a64.x*oy + a64.y*ox + cr.y;
            ox = nx; oy = ny;
        }
    }
    const float* p = d_bu + (size_t)(b*Ss + chunk*64)*256;
    size_t rb = (size_t)(b*Ss + chunk*64);
    float xr = ox, xi = oy;
    if (!dir) {
        for (int s = 0; s < 64; s++) {
            float nr = a.x*xr - a.y*xi + p[s*256+rc];
            float ni = a.x*xi + a.y*xr + p[s*256+ic];
            xr = nr; xi = ni;
            size_t ro = (rb + s)*KCB;
            d_comb[ro+rc] = __float2half_rn(xr);
            d_comb[ro+ic] = __float2half_rn(xi);
        }
    } else {
        for (int s = 63; s >= 0; s--) {
            float nr = a.x*xr - a.y*xi + p[s*256+rc];
            float ni = a.x*xi + a.y*xr + p[s*256+ic];
            xr = nr; xi = ni;
            size_t ro = (rb + s)*KCB;
            d_comb[ro+rc] = __float2half_rn(xr);
            d_comb[ro+ic] = __float2half_rn(xi);
        }
    }
}

// ---------------- launcher ----------------------------------------------------
extern "C" void kernel_launch(void* const* d_in, const int* in_sizes, int n_in,
                              void* d_out, int out_size) {
    const float* x      = (const float*)d_in[0];
    const float* cond   = (const float*)d_in[1];
    const float* f_la   = (const float*)d_in[2];
    const float* f_ai   = (const float*)d_in[3];
    const float* f_br   = (const float*)d_in[4];
    const float* f_bi   = (const float*)d_in[5];
    const float* f_cr   = (const float*)d_in[6];
    const float* f_ci   = (const float*)d_in[7];
    const float* f_d    = (const float*)d_in[8];
    const float* f_ld   = (const float*)d_in[9];
    const float* b_la   = (const float*)d_in[10];
    const float* b_ai   = (const float*)d_in[11];
    const float* b_br   = (const float*)d_in[12];
    const float* b_bi   = (const float*)d_in[13];
    const float* b_cr   = (const float*)d_in[14];
    const float* b_ci   = (const float*)d_in[15];
    const float* b_d    = (const float*)d_in[16];
    const float* b_ld   = (const float*)d_in[17];
    const float* proj_w = (const float*)d_in[18];
    const float* proj_b = (const float*)d_in[19];
    const float* ada_w  = (const float*)d_in[20];
    const float* ada_b  = (const float*)d_in[21];
    const float* mlp_w1 = (const float*)d_in[22];
    const float* mlp_b1 = (const float*)d_in[23];
    const float* mlp_w2 = (const float*)d_in[24];
    const float* mlp_b2 = (const float*)d_in[25];
    float* out = (float*)d_out;

    const int DSM = 2*32768 + 1024;
    cudaFuncSetAttribute(gemm_tc<0>, cudaFuncAttributeMaxDynamicSharedMemorySize, DSM);
    cudaFuncSetAttribute(gemm_tc<1>, cudaFuncAttributeMaxDynamicSharedMemorySize, DSM);
    cudaFuncSetAttribute(gemm_tc<2>, cudaFuncAttributeMaxDynamicSharedMemorySize, DSM);
    cudaFuncSetAttribute(gemm_tc<3>, cudaFuncAttributeMaxDynamicSharedMemorySize, DSM);

    float *bu, *x1; fp16 *comb, *h2, *g, *wbu, *wc, *w1, *w2;
    cudaGetSymbolAddress((void**)&bu, d_bu);
    cudaGetSymbolAddress((void**)&x1, d_x1);
    cudaGetSymbolAddress((void**)&comb, d_comb);
    cudaGetSymbolAddress((void**)&h2, d_h2);
    cudaGetSymbolAddress((void**)&g, d_g);
    cudaGetSymbolAddress((void**)&wbu, d_wbu);
    cudaGetSymbolAddress((void**)&wc, d_wc);
    cudaGetSymbolAddress((void**)&w1, d_w1);
    cudaGetSymbolAddress((void**)&w2, d_w2);

    // 1: merged prep (wc | ssm | transposes | mods)
    prep_all_k<<<2968, 512>>>(cond, ada_w, ada_b,
                              f_la, f_ai, f_br, f_bi, f_ld,
                              b_la, b_ai, b_br, b_bi, b_ld,
                              f_cr, f_ci, b_cr, b_ci, f_d, b_d, proj_w,
                              mlp_w1, mlp_w2);

    // 2: h = modulated LN(x) -> comb cols 256..767
    ln_mod_k<<<BSr, 128>>>(x, comb+256, KCB, 0);

    // 3: Bu[32768,256] = h @ Wbu^T
    gemm_tc<0><<<dim3(2,256), 256, DSM>>>(comb+256, KCB, wbu, Ff, Ff,
                                          bu, 256, nullptr, nullptr, nullptr);
    // 4-5: streaming scan
    scan_carry_k<<<dim3(32,4,2), 256>>>();
    scan_apply_k<<<dim3(32,4,2), 256>>>();

    // 6: x1 = x + g1*(comb @ Wc^T + proj_b)
    gemm_tc<1><<<dim3(4,256), 256, DSM>>>(comb, KCB, wc, KCB, KCB,
                                          x1, Ff, x, proj_b, nullptr);

    // 7: h2 = modulated LN(x1)
    ln_mod_k<<<BSr, 128>>>(x1, h2, Ff, 3*Ff);

    // 8: g = gelu(h2 @ W1^T + b1) -> fp16
    gemm_tc<2><<<dim3(16,256), 256, DSM>>>(h2, Ff, w1, Ff, Ff,
                                           nullptr, Hh, nullptr, mlp_b1, g);

    // 9: out = x1 + g2*(g @ W2^T + b2)
    gemm_tc<3><<<dim3(4,256), 256, DSM>>>(g, Hh, w2, Hh, Hh,
                                          out, Ff, x1, mlp_b2, nullptr);
}

// round 14
// speedup vs baseline: 1.2351x; 1.0019x over previous
#include <cuda_runtime.h>
#include <cuda_fp16.h>
#include <math.h>
#include <stdint.h>

#define Bb 4
#define Ss 8192
#define Ff 512
#define Hh 2048
#define BSr 32768
#define KCB 768
typedef __half fp16;

__device__ __align__(256) fp16   d_bu[(size_t)BSr*256];     // Bu in fp16 (16MB)
__device__ __align__(256) fp16   d_comb[(size_t)BSr*KCB];   // cols 0..255 xs, 256..767 h
__device__ __align__(256) fp16   d_h2[(size_t)BSr*Ff];
__device__ __align__(256) fp16   d_g[(size_t)BSr*Hh];
__device__ __align__(256) float  d_x1[(size_t)BSr*Ff];
__device__ float  d_mods[Bb*6*Ff];
__device__ float2 d_abar[128];
__device__ float2 d_car[Bb*2*128*64];
__device__ __align__(256) fp16   d_wbu[256*Ff];
__device__ __align__(256) fp16   d_wc[Ff*KCB];
__device__ __align__(256) fp16   d_w1[(size_t)Hh*Ff];
__device__ __align__(256) fp16   d_w2[(size_t)Ff*Hh];

__device__ __forceinline__ uint32_t s2u(const void* p){
    uint32_t a;
    asm("{ .reg .u64 t; cvta.to.shared.u64 t, %1; cvt.u32.u64 %0, t; }":"=r"(a):"l"(p));
    return a;
}
__device__ __forceinline__ uint32_t sw64(uint32_t o){ return o ^ ((o >> 3) & 0x30u); }
__device__ __forceinline__ void cpa16(uint32_t d, const void* s){
    asm volatile("cp.async.cg.shared.global [%0], [%1], 16;"::"r"(d),"l"(s));
}
#define CPC() asm volatile("cp.async.commit_group;")
#define CPW(n) asm volatile("cp.async.wait_group %0;"::"n"(n))

__device__ __forceinline__ void ldmx4(uint32_t* r, uint32_t a){
    asm volatile("ldmatrix.sync.aligned.m8n8.x4.shared.b16 {%0,%1,%2,%3}, [%4];"
        :"=r"(r[0]),"=r"(r[1]),"=r"(r[2]),"=r"(r[3]):"r"(a));
}
__device__ __forceinline__ void hmma(float* d, const uint32_t* a, const uint32_t* b){
    asm volatile("mma.sync.aligned.m16n8k16.row.col.f32.f16.f16.f32 "
        "{%0,%1,%2,%3}, {%4,%5,%6,%7}, {%8,%9}, {%0,%1,%2,%3};"
        : "+f"(d[0]),"+f"(d[1]),"+f"(d[2]),"+f"(d[3])
        : "r"(a[0]),"r"(a[1]),"r"(a[2]),"r"(a[3]),"r"(b[0]),"r"(b[1]));
}
// gelu(tanh approx) == x * sigmoid(1.59577*(x + 0.044715 x^3))
__device__ __forceinline__ float fast_gelu(float x){
    float u = x*(1.0f + 0.044715f*x*x);
    float e = __expf(-1.5957691216057308f*u);
    return x * __frcp_rn(1.0f + e);
}

// ---------------- merged prep: blocks [0,768) wc | [768,896) ssm |
//                  [896,2944) transposes | [2944,2968) mods. 512 threads. ----
__global__ __launch_bounds__(512) void prep_all_k(
    const float* __restrict__ cond, const float* __restrict__ aw,
    const float* __restrict__ ab,
    const float* fla, const float* fai, const float* fbr, const float* fbi,
    const float* fld, const float* bla, const float* bai, const float* bbr,
    const float* bbi, const float* bld,
    const float* fcr, const float* fci, const float* bcr, const float* bci,
    const float* Df, const float* Db, const float* pw,
    const float* __restrict__ w1s, const float* __restrict__ w2s)
{
    int bid = blockIdx.x, tid = threadIdx.x;
    if (bid < 768) {
        if (bid < 256) {
            int ch = bid, blk = ch>>6, n = ch&63;
            const float* C = (blk==0)?fcr:(blk==1)?fci:(blk==2)?bcr:bci;
            float sign = (blk==1||blk==3)?-1.0f:1.0f;
            int poff = (blk>=2)?Ff:0;
            __shared__ float sC[Ff];
            sC[tid] = C[tid*64+n];
            __syncthreads();
            float acc = 0.0f;
            #pragma unroll 8
            for (int f = 0; f < Ff; f++) acc += sC[f]*pw[(poff+f)*Ff+tid];
            d_wc[(size_t)tid*KCB+ch] = __float2half_rn(sign*acc);
        } else {
            int idx = (bid - 256)*512 + tid;   // 0..262143
            int f = idx>>9, fp = idx&511;
            float v = Df[f]*pw[idx] + Db[f]*pw[idx+Ff*Ff];
            d_wc[(size_t)fp*KCB+256+f] = __float2half_rn(v);
        }
    } else if (bid < 896) {
        int id = bid - 768;
        int n = id & 63, dir = id >> 6;
        const float* la = dir?bla:fla; const float* ai = dir?bai:fai;
        const float* br = dir?bbr:fbr; const float* bi = dir?bbi:fbi;
        const float* ld = dir?bld:fld;
        float dt = expf(ld[n]), Are = -expf(la[n]), Aim = ai[n];
        float er = expf(Are*dt);
        float abr = er*cosf(Aim*dt), abi = er*sinf(Aim*dt);
        float dre = Are + 1e-8f, dim = Aim;
        float den = dre*dre + dim*dim;
        float nre = abr - 1.0f, nim = abi;
        float cre = (nre*dre + nim*dim)/den, cim = (nim*dre - nre*dim)/den;
        if (tid == 0) d_abar[dir*64+n] = make_float2(abr, abi);
        float bre = br[n*Ff+tid], bim = bi[n*Ff+tid];
        d_wbu[(dir*128+n)*Ff+tid]    = __float2half_rn(cre*bre - cim*bim);
        d_wbu[(dir*128+64+n)*Ff+tid] = __float2half_rn(cre*bim + cim*bre);
    } else if (bid < 2944) {
        int id = bid - 896;
        __shared__ float t[32][33];
        const float* s; fp16* d; int R, C, bx, by;
        if (id < 1024) { s = w1s; d = d_w1; R = Ff; C = Hh; bx = (id & 63)*32; by = (id >> 6)*32; }
        else { id -= 1024; s = w2s; d = d_w2; R = Hh; C = Ff; bx = (id & 15)*32; by = (id >> 4)*32; }
        int tx = tid & 31, ty = tid >> 5;   // ty 0..15
        #pragma unroll
        for (int i = 0; i < 32; i += 16) t[ty+i][tx] = s[(size_t)(by+ty+i)*C + bx+tx];
        __syncthreads();
        #pragma unroll
        for (int i = 0; i < 32; i += 16)
            d[(size_t)(bx+ty+i)*R + by+tx] = __float2half_rn(t[tx][ty+i]);
    } else {
        int id = bid - 2944;              // 0..23
        int b = id / 6, seg = id % 6;
        __shared__ float sc[Ff];
        sc[tid] = 0.0f;
        float v = cond[b*Ff + tid];
        sc[tid] = v * __frcp_rn(1.0f + __expf(-v));
        __syncthreads();
        int j = seg*512 + tid;            // 0..3071
        float acc = ab[j];
        #pragma unroll 8
        for (int f = 0; f < Ff; f++) acc += sc[f]*aw[f*(6*Ff)+j];
        d_mods[b*(6*Ff)+j] = acc;
    }
}

__global__ void ln_mod_k(const float* __restrict__ in, fp16* __restrict__ oh,
                         int ld, int moff) {
    int row = blockIdx.x, bb = row>>13, tid = threadIdx.x;
    float4 v = ((const float4*)(in + (size_t)row*Ff))[tid];
    float s = v.x+v.y+v.z+v.w, sq = v.x*v.x+v.y*v.y+v.z*v.z+v.w*v.w;
    #pragma unroll
    for (int o = 16; o > 0; o >>= 1) {
        s += __shfl_down_sync(~0u, s, o); sq += __shfl_down_sync(~0u, sq, o);
    }
    __shared__ float ss[4], sv[4];
    int w = tid>>5, l = tid&31;
    if (l==0){ ss[w]=s; sv[w]=sq; }
    __syncthreads();
    if (tid==0){ ss[0]+=ss[1]+ss[2]+ss[3]; sv[0]+=sv[1]+sv[2]+sv[3]; }
    __syncthreads();
    float mu = ss[0]*(1.0f/512.0f), var = sv[0]*(1.0f/512.0f) - mu*mu;
    float rs = rsqrtf(var + 1e-5f);
    const float* md = d_mods + bb*(6*Ff) + moff;
    int f = tid*4;
    float o0 = (v.x-mu)*rs*(1.0f+md[Ff+f+0]) + md[f+0];
    float o1 = (v.y-mu)*rs*(1.0f+md[Ff+f+1]) + md[f+1];
    float o2 = (v.z-mu)*rs*(1.0f+md[Ff+f+2]) + md[f+2];
    float o3 = (v.w-mu)*rs*(1.0f+md[Ff+f+3]) + md[f+3];
    fp16 h4[4] = {__float2half_rn(o0), __float2half_rn(o1),
                  __float2half_rn(o2), __float2half_rn(o3)};
    *(uint2*)&oh[(size_t)row*ld + f] = *(uint2*)h4;
}

// ---------------- HMMA GEMM (R7 champion config) ------------------------------
__device__ __forceinline__ void load_sub(uint32_t b,
    const fp16* __restrict__ A, int lda, const fp16* __restrict__ B, int ldb,
    int m0, int n0, int kc, int tid) {
    #pragma unroll
    for (int i = 0; i < 2; i++) {
        int idx = tid + i*256;            // 0..511
        int row = idx >> 2, c16 = idx & 3;
        uint32_t o = sw64((uint32_t)(row*64 + c16*16));
        cpa16(b + o,        A + (size_t)(m0+row)*lda + kc + c16*8);
        cpa16(b + 8192 + o, B + (size_t)(n0+row)*ldb + kc + c16*8);
    }
}
__device__ __forceinline__ void load_stage(uint32_t b,
    const fp16* __restrict__ A, int lda, const fp16* __restrict__ B, int ldb,
    int m0, int n0, int kc, int tid) {
    load_sub(b,         A, lda, B, ldb, m0, n0, kc,      tid);
    load_sub(b + 16384, A, lda, B, ldb, m0, n0, kc + 32, tid);
}

// EPI: 0 fp32 C  1 x1=aux1+g1*(v+aux2)  2 gelu(v+aux2)->fp16  3 aux1+g2*(v+aux2)
//      4 plain fp16 store (Bu)
template<int EPI>
__global__ __launch_bounds__(256, 2) void gemm_tc(
    const fp16* __restrict__ A, int lda,
    const fp16* __restrict__ B, int ldb, int K,
    float* __restrict__ C, int ldc, const float* __restrict__ aux1,
    const float* __restrict__ aux2, fp16* __restrict__ obh)
{
    extern __shared__ char dsm[];
    uint32_t sb = (s2u(dsm) + 1023u) & ~1023u;
    int tid = threadIdx.x;
    int n0 = blockIdx.x*128, m0 = blockIdx.y*128;
    int wid = tid>>5, lane = tid&31;
    int wm = wid>>2, wn = wid&3;

    float acc[4][4][4];
    #pragma unroll
    for (int a = 0; a < 4; a++)
        #pragma unroll
        for (int bq = 0; bq < 4; bq++)
            #pragma unroll
            for (int r = 0; r < 4; r++) acc[a][bq][r] = 0.0f;

    const int NC = K >> 6;
    load_stage(sb, A, lda, B, ldb, m0, n0, 0, tid);
    CPC();
    for (int c = 0; c < NC; c++) {
        uint32_t cur = sb + (uint32_t)(c & 1)*32768u;
        if (c + 1 < NC) {
            load_stage(sb + (uint32_t)((c+1)&1)*32768u, A, lda, B, ldb,
                       m0, n0, (c+1)<<6, tid);
            CPC();
            CPW(1);
        } else {
            CPW(0);
        }
        __syncthreads();
        #pragma unroll
        for (int ks4 = 0; ks4 < 4; ks4++) {
            uint32_t sub = cur + (uint32_t)(ks4 >> 1)*16384u;
            int ks = ks4 & 1;
            uint32_t af[4][4], bf[4][2];
            #pragma unroll
            for (int mt = 0; mt < 4; mt++) {
                int row = wm*64 + mt*16 + (lane & 15);
                int ch  = ks*2 + (lane >> 4);
                ldmx4(af[mt], sub + sw64((uint32_t)(row*64 + ch*16)));
            }
            #pragma unroll
            for (int bp = 0; bp < 2; bp++) {
                int mi = lane >> 3;
                int row = wn*32 + bp*16 + (mi >> 1)*8 + (lane & 7);
                int ch  = ks*2 + (mi & 1);
                uint32_t r[4];
                ldmx4(r, sub + 8192 + sw64((uint32_t)(row*64 + ch*16)));
                bf[bp*2][0]=r[0]; bf[bp*2][1]=r[1]; bf[bp*2+1][0]=r[2]; bf[bp*2+1][1]=r[3];
            }
            #pragma unroll
            for (int mt = 0; mt < 4; mt++)
                #pragma unroll
                for (int nt = 0; nt < 4; nt++)
                    hmma(acc[mt][nt], af[mt], bf[nt]);
        }
        __syncthreads();
    }

    int g = lane >> 2, tig = lane & 3;
    #pragma unroll
    for (int mt = 0; mt < 4; mt++) {
        #pragma unroll
        for (int nt = 0; nt < 4; nt++) {
            int n = n0 + wn*32 + nt*8 + tig*2;
            #pragma unroll
            for (int half = 0; half < 2; half++) {
                int m = m0 + wm*64 + mt*16 + g + half*8;
                float v0 = acc[mt][nt][half*2+0], v1 = acc[mt][nt][half*2+1];
                if (EPI == 0) {
                    float2 o = {v0, v1};
                    *(float2*)&C[(size_t)m*ldc + n] = o;
                } else if (EPI == 1 || EPI == 3) {
                    int bb = m >> 13;
                    const float* md = d_mods + bb*(6*Ff) + (EPI==1 ? 2*Ff : 5*Ff);
                    float2 o;
                    o.x = aux1[(size_t)m*Ff + n+0] + md[n+0]*(v0 + aux2[n+0]);
                    o.y = aux1[(size_t)m*Ff + n+1] + md[n+1]*(v1 + aux2[n+1]);
                    *(float2*)&C[(size_t)m*ldc + n] = o;
                } else if (EPI == 2) {
                    fp16 hp[2];
                    hp[0] = __float2half_rn(fast_gelu(v0 + aux2[n+0]));
                    hp[1] = __float2half_rn(fast_gelu(v1 + aux2[n+1]));
                    *(uint32_t*)&obh[(size_t)m*ldc + n] = *(uint32_t*)hp;
                } else {
                    fp16 hp[2];
                    hp[0] = __float2half_rn(v0);
                    hp[1] = __float2half_rn(v1);
                    *(uint32_t*)&obh[(size_t)m*ldc + n] = *(uint32_t*)hp;
                }
            }
        }
    }
}

// ---------------- streaming scan over fp16 Bu[32768][256] --------------------
__global__ __launch_bounds__(256) void scan_carry_k() {
    int t = threadIdx.x;
    int c = t & 63;
    int chunk = blockIdx.x*4 + (t>>6);
    int b = blockIdx.y, dir = blockIdx.z;
    int rc = dir ? 128+c : c, ic = rc+64;
    float2 a = d_abar[dir*64+c];
    const fp16* p = d_bu + (size_t)(b*Ss + chunk*64)*256;
    float xr = 0.0f, xi = 0.0f;
    if (!dir) {
        for (int s = 0; s < 64; s++) {
            float ur = __half2float(p[s*256+rc]), ui = __half2float(p[s*256+ic]);
            float nr = a.x*xr - a.y*xi + ur;
            float ni = a.x*xi + a.y*xr + ui;
            xr = nr; xi = ni;
        }
    } else {
        float px = 1.0f, py = 0.0f;
        for (int s = 0; s < 64; s++) {
            float ur = __half2float(p[s*256+rc]), ui = __half2float(p[s*256+ic]);
            xr += px*ur - py*ui;
            xi += px*ui + py*ur;
            float np = px*a.x - py*a.y;
            py = px*a.y + py*a.x; px = np;
        }
    }
    d_car[(((size_t)(b*2+dir))*128 + chunk)*64 + c] = make_float2(xr, xi);
}

__global__ __launch_bounds__(256) void scan_apply_k() {
    int t = threadIdx.x;
    int c = t & 63;
    int chunk = blockIdx.x*4 + (t>>6);
    int b = blockIdx.y, dir = blockIdx.z;
    int rc = dir ? 128+c : c, ic = rc+64;
    float2 a = d_abar[dir*64+c];
    float2 a64 = a;
    #pragma unroll
    for (int i = 0; i < 6; i++) {
        float tq = a64.x*a64.x - a64.y*a64.y;
        a64.y = 2.0f*a64.x*a64.y; a64.x = tq;
    }
    size_t base = ((size_t)(b*2+dir))*128*64 + c;
    float ox = 0.0f, oy = 0.0f;
    if (!dir) {
        for (int ch = 0; ch < chunk; ch++) {
            float2 cr = d_car[base + (size_t)ch*64];
            float nx = a64.x*ox - a64.y*oy + cr.x;
            float ny = a64.x*oy + a64.y*ox + cr.y;
            ox = nx; oy = ny;
        }
    } else {
        for (int ch = 127; ch > chunk; ch--) {
            float2 cr = d_car[base + (size_t)ch*64];
            float nx = a64.x*ox - a64.y*oy + cr.x;
            float ny = a64.x*oy + a64.y*ox + cr.y;
            ox = nx; oy = ny;
        }
    }
    const fp16* p = d_bu + (size_t)(b*Ss + chunk*64)*256;
    size_t rb = (size_t)(b*Ss + chunk*64);
    float xr = ox, xi = oy;
    if (!dir) {
        for (int s = 0; s < 64; s++) {
            float nr = a.x*xr - a.y*xi + __half2float(p[s*256+rc]);
            float ni = a.x*xi + a.y*xr + __half2float(p[s*256+ic]);
            xr = nr; xi = ni;
            size_t ro = (rb + s)*KCB;
            d_comb[ro+rc] = __float2half_rn(xr);
            d_comb[ro+ic] = __float2half_rn(xi);
        }
    } else {
        for (int s = 63; s >= 0; s--) {
            float nr = a.x*xr - a.y*xi + __half2float(p[s*256+rc]);
            float ni = a.x*xi + a.y*xr + __half2float(p[s*256+ic]);
            xr = nr; xi = ni;
            size_t ro = (rb + s)*KCB;
            d_comb[ro+rc] = __float2half_rn(xr);
            d_comb[ro+ic] = __float2half_rn(xi);
        }
    }
}

// ---------------- launcher ----------------------------------------------------
extern "C" void kernel_launch(void* const* d_in, const int* in_sizes, int n_in,
                              void* d_out, int out_size) {
    const float* x      = (const float*)d_in[0];
    const float* cond   = (const float*)d_in[1];
    const float* f_la   = (const float*)d_in[2];
    const float* f_ai   = (const float*)d_in[3];
    const float* f_br   = (const float*)d_in[4];
    const float* f_bi   = (const float*)d_in[5];
    const float* f_cr   = (const float*)d_in[6];
    const float* f_ci   = (const float*)d_in[7];
    const float* f_d    = (const float*)d_in[8];
    const float* f_ld   = (const float*)d_in[9];
    const float* b_la   = (const float*)d_in[10];
    const float* b_ai   = (const float*)d_in[11];
    const float* b_br   = (const float*)d_in[12];
    const float* b_bi   = (const float*)d_in[13];
    const float* b_cr   = (const float*)d_in[14];
    const float* b_ci   = (const float*)d_in[15];
    const float* b_d    = (const float*)d_in[16];
    const float* b_ld   = (const float*)d_in[17];
    const float* proj_w = (const float*)d_in[18];
    const float* proj_b = (const float*)d_in[19];
    const float* ada_w  = (const float*)d_in[20];
    const float* ada_b  = (const float*)d_in[21];
    const float* mlp_w1 = (const float*)d_in[22];
    const float* mlp_b1 = (const float*)d_in[23];
    const float* mlp_w2 = (const float*)d_in[24];
    const float* mlp_b2 = (const float*)d_in[25];
    float* out = (float*)d_out;

    const int DSM = 2*32768 + 1024;
    cudaFuncSetAttribute(gemm_tc<1>, cudaFuncAttributeMaxDynamicSharedMemorySize, DSM);
    cudaFuncSetAttribute(gemm_tc<2>, cudaFuncAttributeMaxDynamicSharedMemorySize, DSM);
    cudaFuncSetAttribute(gemm_tc<3>, cudaFuncAttributeMaxDynamicSharedMemorySize, DSM);
    cudaFuncSetAttribute(gemm_tc<4>, cudaFuncAttributeMaxDynamicSharedMemorySize, DSM);

    float *x1; fp16 *bu, *comb, *h2, *g, *wbu, *wc, *w1, *w2;
    cudaGetSymbolAddress((void**)&bu, d_bu);
    cudaGetSymbolAddress((void**)&x1, d_x1);
    cudaGetSymbolAddress((void**)&comb, d_comb);
    cudaGetSymbolAddress((void**)&h2, d_h2);
    cudaGetSymbolAddress((void**)&g, d_g);
    cudaGetSymbolAddress((void**)&wbu, d_wbu);
    cudaGetSymbolAddress((void**)&wc, d_wc);
    cudaGetSymbolAddress((void**)&w1, d_w1);
    cudaGetSymbolAddress((void**)&w2, d_w2);

    // 1: merged prep (wc | ssm | transposes | mods)
    prep_all_k<<<2968, 512>>>(cond, ada_w, ada_b,
                              f_la, f_ai, f_br, f_bi, f_ld,
                              b_la, b_ai, b_br, b_bi, b_ld,
                              f_cr, f_ci, b_cr, b_ci, f_d, b_d, proj_w,
                              mlp_w1, mlp_w2);

    // 2: h = modulated LN(x) -> comb cols 256..767
    ln_mod_k<<<BSr, 128>>>(x, comb+256, KCB, 0);

    // 3: Bu[32768,256] = h @ Wbu^T  (fp16 output)
    gemm_tc<4><<<dim3(2,256), 256, DSM>>>(comb+256, KCB, wbu, Ff, Ff,
                                          nullptr, 256, nullptr, nullptr, bu);
    // 4-5: streaming scan over fp16 Bu
    scan_carry_k<<<dim3(32,4,2), 256>>>();
    scan_apply_k<<<dim3(32,4,2), 256>>>();

    // 6: x1 = x + g1*(comb @ Wc^T + proj_b)
    gemm_tc<1><<<dim3(4,256), 256, DSM>>>(comb, KCB, wc, KCB, KCB,
                                          x1, Ff, x, proj_b, nullptr);

    // 7: h2 = modulated LN(x1)
    ln_mod_k<<<BSr, 128>>>(x1, h2, Ff, 3*Ff);

    // 8: g = gelu(h2 @ W1^T + b1) -> fp16
    gemm_tc<2><<<dim3(16,256), 256, DSM>>>(h2, Ff, w1, Ff, Ff,
                                           nullptr, Hh, nullptr, mlp_b1, g);

    // 9: out = x1 + g2*(g @ W2^T + b2)
    gemm_tc<3><<<dim3(4,256), 256, DSM>>>(g, Hh, w2, Hh, Hh,
                                          out, Ff, x1, mlp_b2, nullptr);
}